// round 14
// baseline (speedup 1.0000x reference)
#include <cuda_runtime.h>
#include <math.h>
#include <stdint.h>

#define BATCH 4
#define SEQ   2048
#define DIM   1024
#define NHEAD 16
#define HD    64
#define ROWS  (BATCH*SEQ)   // 8192

// ---------------- scratch (device globals; no allocation allowed) ----------
__device__ float g_Qbuf[(size_t)ROWS * DIM];
__device__ float g_KVbuf[(size_t)ROWS * 2 * DIM];
__device__ float g_Q[(size_t)ROWS * DIM];           // [B,H,S,Hd] tf32
__device__ float g_K[(size_t)ROWS * DIM];           // [B,H,Sc,Hd] tf32
__device__ float g_V[(size_t)ROWS * DIM];           // [B,H,Hd,Sc] transposed tf32
__device__ float g_O[(size_t)ROWS * DIM];           // [B,S,H*Hd] raw fp32
__device__ float g_qwt[(size_t)DIM * DIM];          // q_w^T   [N][K] tf32
__device__ float g_kvwt[(size_t)2 * DIM * DIM];     // kv_w^T  [2N][K] tf32
__device__ float g_pwt[(size_t)DIM * DIM];          // proj_w^T tf32

// ---------------- helpers ---------------------------------------------------
__device__ __forceinline__ unsigned tf32(float x) {
    unsigned u;
    asm("cvt.rna.tf32.f32 %0, %1;" : "=r"(u) : "f"(x));
    return u;
}
__device__ __forceinline__ float tf32f(float x) { return __uint_as_float(tf32(x)); }
__device__ __forceinline__ float ex2(float x) {
    float y;
    asm("ex2.approx.f32 %0, %1;" : "=f"(y) : "f"(x));
    return y;
}

__device__ __forceinline__ void mma8(float* d, const unsigned* a, const unsigned* b) {
    asm volatile(
        "mma.sync.aligned.m16n8k8.row.col.f32.tf32.tf32.f32 "
        "{%0,%1,%2,%3}, {%4,%5,%6,%7}, {%8,%9}, {%0,%1,%2,%3};"
        : "+f"(d[0]), "+f"(d[1]), "+f"(d[2]), "+f"(d[3])
        : "r"(a[0]), "r"(a[1]), "r"(a[2]), "r"(a[3]), "r"(b[0]), "r"(b[1]));
}
__device__ __forceinline__ void mma8b(float* d, const unsigned* a,
                                      unsigned b0, unsigned b1) {
    asm volatile(
        "mma.sync.aligned.m16n8k8.row.col.f32.tf32.tf32.f32 "
        "{%0,%1,%2,%3}, {%4,%5,%6,%7}, {%8,%9}, {%0,%1,%2,%3};"
        : "+f"(d[0]), "+f"(d[1]), "+f"(d[2]), "+f"(d[3])
        : "r"(a[0]), "r"(a[1]), "r"(a[2]), "r"(a[3]), "r"(b0), "r"(b1));
}
__device__ __forceinline__ void ldsm4(unsigned* r, uint32_t addr) {
    asm volatile("ldmatrix.sync.aligned.m8n8.x4.shared.b16 {%0,%1,%2,%3}, [%4];"
        : "=r"(r[0]), "=r"(r[1]), "=r"(r[2]), "=r"(r[3]) : "r"(addr));
}
__device__ __forceinline__ void cpa16(uint32_t s, const void* g) {
    asm volatile("cp.async.cg.shared.global [%0], [%1], 16;" :: "r"(s), "l"(g));
}
__device__ __forceinline__ void cpa_commit() {
    asm volatile("cp.async.commit_group;");
}
__device__ __forceinline__ uint32_t sptr(const void* p) {
    return (uint32_t)__cvta_generic_to_shared(p);
}

// ---------------- prep: transpose + tf32-round the 3 weights ---------------
__global__ void prep_kernel(
        const float* __restrict__ qw,  const float* __restrict__ pw,
        const float* __restrict__ kvw,
        float* __restrict__ qwt, float* __restrict__ pwt,
        float* __restrict__ kvwt) {
    const int z = blockIdx.z;
    const float* W; float* Wt; int N;
    if (z == 0)      { W = qw;  Wt = qwt;  N = DIM; }
    else if (z == 1) { W = pw;  Wt = pwt;  N = DIM; }
    else             { W = kvw; Wt = kvwt; N = 2 * DIM; }
    const int ntx = N / 32;
    const int tile = blockIdx.x;
    if (tile >= (DIM / 32) * ntx) return;
    const int kx = (tile / ntx) * 32, ny = (tile % ntx) * 32;
    __shared__ float t[32][33];
    const int tx = threadIdx.x & 31, ty = threadIdx.x >> 5;
#pragma unroll
    for (int j = 0; j < 32; j += 8)
        t[ty + j][tx] = tf32f(W[(size_t)(kx + ty + j) * N + ny + tx]);
    __syncthreads();
#pragma unroll
    for (int j = 0; j < 32; j += 8)
        Wt[(size_t)(ny + ty + j) * DIM + kx + tx] = t[tx][ty + j];
}

// ---------------- TF32 GEMM core: C = A @ Bt^T (+bias) ---------------------
// A raw fp32 (fragments cvt'd to tf32 post-ldsm); Bt pre-transposed+rounded.
// K-tile 16, 3-stage cp.async, prefetch mid-slab. 8 warps (2m x 4n).
#define TSTR 20
#define OP_SZ (128*TSTR)
#define STG_B (2*OP_SZ*4)
#define GEMM_SMEM (3*STG_B)            // 61440 B

__device__ __forceinline__ void gemm_core(
        const float* __restrict__ A, const float* __restrict__ Bt,
        const float* __restrict__ bias, float* __restrict__ C,
        int N, int K, float* sm, int bx, int by) {
    const int tid  = threadIdx.x;
    const int warp = tid >> 5, lane = tid & 31;
    const int g = lane >> 2, c = lane & 3;
    const int wm = (warp >> 2) * 64, wn = (warp & 3) * 32;
    const int bm = by * 128, bn = bx * 128;

    const int ar  = tid >> 2;
    const int ac4 = (tid & 3) << 2;

    const float* Ap = A  + (size_t)(bm + ar) * K + ac4;
    const float* Bp = Bt + (size_t)(bn + ar) * K + ac4;

    const uint32_t s0 = sptr(sm);
    const uint32_t cpA0 = s0 + (ar * TSTR + ac4) * 4;
    const uint32_t cpA1 = cpA0 + 64 * TSTR * 4;
    const uint32_t cpB0 = cpA0 + OP_SZ * 4;
    const uint32_t cpB1 = cpB0 + 64 * TSTR * 4;

    const int mloc = lane >> 3, rw = lane & 7;
    const uint32_t ard = s0 +
        ((wm + ((mloc & 1) << 3) + rw) * TSTR + ((mloc >> 1) << 2)) * 4;
    const uint32_t brd = s0 + OP_SZ * 4 +
        ((wn + ((lane >> 4) << 3) + rw) * TSTR + (((lane >> 3) & 1) << 2)) * 4;

    float acc[4][4][4];
#pragma unroll
    for (int mi = 0; mi < 4; mi++)
#pragma unroll
        for (int ni = 0; ni < 4; ni++)
#pragma unroll
            for (int t = 0; t < 4; t++) acc[mi][ni][t] = 0.f;

    const int nT = K >> 4;
    auto issue = [&](int t) {
        const uint32_t off = (uint32_t)(t % 3) * STG_B;
        const int k0 = t << 4;
        cpa16(cpA0 + off, Ap + k0);
        cpa16(cpA1 + off, Ap + (size_t)64 * K + k0);
        cpa16(cpB0 + off, Bp + k0);
        cpa16(cpB1 + off, Bp + (size_t)64 * K + k0);
    };

    issue(0); cpa_commit();
    issue(1); cpa_commit();

    for (int t = 0; t < nT; t++) {
        asm volatile("cp.async.wait_group 1;");
        __syncthreads();

        const uint32_t off = (uint32_t)(t % 3) * STG_B;

        // ---- k-step 0 ----
        {
            unsigned af[4][4], bfr[8];
#pragma unroll
            for (int mi = 0; mi < 4; mi++)
                ldsm4(af[mi], ard + off + mi * (16 * TSTR * 4));
            ldsm4(bfr,     brd + off);
            ldsm4(bfr + 4, brd + off + 16 * TSTR * 4);
#pragma unroll
            for (int mi = 0; mi < 4; mi++)
#pragma unroll
                for (int t2 = 0; t2 < 4; t2++)
                    af[mi][t2] = tf32(__uint_as_float(af[mi][t2]));
#pragma unroll
            for (int mi = 0; mi < 4; mi++)
#pragma unroll
                for (int ni = 0; ni < 4; ni++)
                    mma8b(acc[mi][ni], af[mi], bfr[2 * ni], bfr[2 * ni + 1]);
        }

        if (t + 2 < nT) issue(t + 2);
        cpa_commit();

        // ---- k-step 1 ----
        {
            unsigned af[4][4], bfr[8];
#pragma unroll
            for (int mi = 0; mi < 4; mi++)
                ldsm4(af[mi], ard + off + mi * (16 * TSTR * 4) + 32);
            ldsm4(bfr,     brd + off + 32);
            ldsm4(bfr + 4, brd + off + 16 * TSTR * 4 + 32);
#pragma unroll
            for (int mi = 0; mi < 4; mi++)
#pragma unroll
                for (int t2 = 0; t2 < 4; t2++)
                    af[mi][t2] = tf32(__uint_as_float(af[mi][t2]));
#pragma unroll
            for (int mi = 0; mi < 4; mi++)
#pragma unroll
                for (int ni = 0; ni < 4; ni++)
                    mma8b(acc[mi][ni], af[mi], bfr[2 * ni], bfr[2 * ni + 1]);
        }
    }

#pragma unroll
    for (int mi = 0; mi < 4; mi++) {
        int row = bm + wm + mi * 16 + g;
#pragma unroll
        for (int ni = 0; ni < 4; ni++) {
            int col = bn + wn + ni * 8 + 2 * c;
            float bv0 = bias ? bias[col] : 0.f;
            float bv1 = bias ? bias[col + 1] : 0.f;
            float* p0 = C + (size_t)row * N + col;
            float* p1 = C + (size_t)(row + 8) * N + col;
            p0[0] = acc[mi][ni][0] + bv0; p0[1] = acc[mi][ni][1] + bv1;
            p1[0] = acc[mi][ni][2] + bv0; p1[1] = acc[mi][ni][3] + bv1;
        }
    }
}

// fused q+kv projections: bx<8 -> q (N=1024), bx>=8 -> kv (N=2048)
__global__ __launch_bounds__(256) void gemm_qkv(
        const float* __restrict__ X, const float* __restrict__ Cc,
        const float* __restrict__ Bq, const float* __restrict__ Bkv,
        float* __restrict__ Cq, float* __restrict__ Ckv) {
    extern __shared__ float sm[];
    if (blockIdx.x < 8)
        gemm_core(X, Bq, nullptr, Cq, DIM, DIM, sm, blockIdx.x, blockIdx.y);
    else
        gemm_core(Cc, Bkv, nullptr, Ckv, 2 * DIM, DIM, sm,
                  blockIdx.x - 8, blockIdx.y);
}

__global__ __launch_bounds__(256) void gemm_tf32(
        const float* __restrict__ A, const float* __restrict__ Bt,
        const float* __restrict__ bias, float* __restrict__ C,
        int N, int K) {
    extern __shared__ float sm[];
    gemm_core(A, Bt, bias, C, N, K, sm, blockIdx.x, blockIdx.y);
}

// ---------------- fused LN: q-mode (LN+RoPE) and kv-mode (LN k + V^T) ------
__global__ __launch_bounds__(256) void ln_all_kernel(
        const float* __restrict__ Qbuf, const float* __restrict__ KVbuf,
        const float* __restrict__ qg, const float* __restrict__ qb,
        const float* __restrict__ kg, const float* __restrict__ kb_,
        float* __restrict__ Q, float* __restrict__ K, float* __restrict__ Vt) {
    const int h = blockIdx.y, rb = blockIdx.x * 64;
    const int tid = threadIdx.x, warp = tid >> 5, lane = tid & 31;

    if (blockIdx.z >= 4) {
        const int b = blockIdx.z - 4;
        const float ga0 = qg[lane], ga1 = qg[lane + 32];
        const float be0 = qb[lane], be1 = qb[lane + 32];
        const float invf = ex2(-(float)lane * (13.28771237954945f / 32.f));
#pragma unroll
        for (int j = 0; j < 8; j++) {
            const int s = rb + warp * 8 + j;
            const float* in = Qbuf + ((size_t)b * SEQ + s) * DIM + h * HD;
            float v0 = in[lane], v1 = in[lane + 32];
            float sum = v0 + v1;
#pragma unroll
            for (int o = 16; o; o >>= 1) sum += __shfl_xor_sync(0xffffffffu, sum, o);
            float mu = sum * (1.f / 64.f);
            float d0 = v0 - mu, d1 = v1 - mu;
            float vs = d0 * d0 + d1 * d1;
#pragma unroll
            for (int o = 16; o; o >>= 1) vs += __shfl_xor_sync(0xffffffffu, vs, o);
            float rstd = rsqrtf(vs * (1.f / 64.f) + 1e-5f);
            float y0 = d0 * rstd * ga0 + be0;
            float y1 = d1 * rstd * ga1 + be1;
            float sn, cs;
            sincosf((float)s * invf, &sn, &cs);
            float* outp = Q + ((size_t)(b * NHEAD + h) * SEQ + s) * HD;
            outp[lane]      = tf32f(y0 * cs - y1 * sn);
            outp[lane + 32] = tf32f(y0 * sn + y1 * cs);
        }
        return;
    }

    __shared__ float Vs[64 * 65];
    const int b = blockIdx.z;
    const float ga0 = kg[lane], ga1 = kg[lane + 32];
    const float be0 = kb_[lane], be1 = kb_[lane + 32];
#pragma unroll
    for (int j = 0; j < 8; j++) {
        const int kl  = warp * 8 + j;
        const int key = rb + kl;
        const float* kin = KVbuf + ((size_t)b * SEQ + key) * (2 * DIM) + h * HD;
        const float* vin = kin + DIM;
        float v0 = kin[lane], v1 = kin[lane + 32];
        float sum = v0 + v1;
#pragma unroll
        for (int o = 16; o; o >>= 1) sum += __shfl_xor_sync(0xffffffffu, sum, o);
        float mu = sum * (1.f / 64.f);
        float d0 = v0 - mu, d1 = v1 - mu;
        float vs = d0 * d0 + d1 * d1;
#pragma unroll
        for (int o = 16; o; o >>= 1) vs += __shfl_xor_sync(0xffffffffu, vs, o);
        float rstd = rsqrtf(vs * (1.f / 64.f) + 1e-5f);
        size_t ob = ((size_t)(b * NHEAD + h) * SEQ + key) * HD;
        K[ob + lane]      = tf32f(d0 * rstd * ga0 + be0);
        K[ob + lane + 32] = tf32f(d1 * rstd * ga1 + be1);
        Vs[lane * 65 + kl]        = tf32f(vin[lane]);
        Vs[(lane + 32) * 65 + kl] = tf32f(vin[lane + 32]);
    }
    __syncthreads();
    const int d = tid >> 2, c0 = (tid & 3) * 16;
    float* dst = Vt + ((size_t)((b * NHEAD + h) * HD + d)) * SEQ + rb + c0;
#pragma unroll
    for (int e = 0; e < 16; e += 4) {
        const float* s = &Vs[d * 65 + c0 + e];
        *(float4*)(dst + e) = make_float4(s[0], s[1], s[2], s[3]);
    }
}

// --------- flash attention: 128q x 64k, 4 warps x 32 rows (R12 form) -------
#define QIDX(r, col) ((r) * 64 + ((col) ^ (((r) & 7) << 2)))
#define VTIDX(d, key) ((d) * 64 + (((((key) >> 2) ^ ((d) & 7)) << 2) | ((key) & 3)))
#define FKV 8192
#define PWARP 2048
#define FLASH_SMEM ((2*FKV + 4*PWARP)*4)    // 98304 B

#define QSCALE (0.125f * 1.44269504088896340736f)

__global__ __launch_bounds__(128, 2) void flash_tf32(
        const float* __restrict__ Q, const float* __restrict__ K,
        const float* __restrict__ Vt, float* __restrict__ O) {
    extern __shared__ float stage[];

    const int qt = blockIdx.x, h = blockIdx.y, b = blockIdx.z;
    const int tid  = threadIdx.x;
    const int warp = tid >> 5, lane = tid & 31;
    const int g = lane >> 2, c = lane & 3;
    const int wm = warp * 32;

    const int mloc = lane >> 3, rw = lane & 7;
    uint32_t kb_base[4];
#pragma unroll
    for (int gi = 0; gi < 4; gi++) {
        int row = (gi * 2 + (mloc >> 1)) * 8 + rw;
        kb_base[gi] = (uint32_t)(row * 256) + ((((mloc & 1) << 4) ^ (rw << 4)));
    }
    const int Lr = lane & 15, h4 = lane >> 4, mmv = lane & 7;
    uint32_t vrow[4];
#pragma unroll
    for (int gi = 0; gi < 4; gi++) vrow[gi] = (uint32_t)((16 * gi + Lr) * 256);
    const uint32_t vlc = ((uint32_t)h4 << 4) ^ ((uint32_t)mmv << 4);
    float* Pw = stage + 2 * FKV + warp * PWARP;
    const uint32_t pwb = sptr(Pw);
    const uint32_t p_row = (uint32_t)((((lane >> 3) & 1) * 8 + rw) * 256);
    const uint32_t p_hi  = (uint32_t)((lane >> 4) << 4);
    const uint32_t p_rsw = (uint32_t)(rw << 4);

    const float* Qg  = Q  + ((size_t)(b * NHEAD + h) * SEQ + qt * 128) * HD;
    const float* Kg  = K  + (size_t)(b * NHEAD + h) * SEQ * HD;
    const float* Vtg = Vt + (size_t)(b * NHEAD + h) * HD * SEQ;

#pragma unroll
    for (int j = 0; j < 16; j++) {
        int i = tid + j * 128;
        int r = i >> 4, c4 = (i & 15) << 2;
        float* dst = (r < 64) ? &stage[QIDX(r, c4)] : &stage[4096 + QIDX(r - 64, c4)];
        cpa16(sptr(dst), Qg + (size_t)r * 64 + c4);
    }
    cpa_commit();
    asm volatile("cp.async.wait_group 0;");
    __syncthreads();

    unsigned qf[2][8][4];
#pragma unroll
    for (int mt = 0; mt < 2; mt++) {
        const int rbase = wm + mt * 16;
        const float* buf = (rbase < 64) ? stage : stage + 4096;
        const int rb = rbase & 63;
#pragma unroll
        for (int ks = 0; ks < 8; ks++) {
            int kk = ks * 8 + c;
            qf[mt][ks][0] = tf32(QSCALE * buf[QIDX(rb + g, kk)]);
            qf[mt][ks][1] = tf32(QSCALE * buf[QIDX(rb + 8 + g, kk)]);
            qf[mt][ks][2] = tf32(QSCALE * buf[QIDX(rb + g, kk + 4)]);
            qf[mt][ks][3] = tf32(QSCALE * buf[QIDX(rb + 8 + g, kk + 4)]);
        }
    }
    __syncthreads();

    auto issueKV = [&](int t) {
        float* Kb = stage + (t & 1) * FKV;
        float* Vb = Kb + 4096;
#pragma unroll
        for (int j = 0; j < 8; j++) {
            int i = tid + j * 128;
            int r = i >> 4, c4 = (i & 15) << 2;
            cpa16(sptr(&Kb[QIDX(r, c4)]), Kg + (size_t)(t * 64 + r) * 64 + c4);
            cpa16(sptr(&Vb[VTIDX(r, c4)]), Vtg + (size_t)r * SEQ + t * 64 + c4);
        }
    };

    issueKV(0); cpa_commit();
    issueKV(1); cpa_commit();

    float m_[2][2], l_[2][2], o[2][8][4];
#pragma unroll
    for (int mt = 0; mt < 2; mt++) {
        m_[mt][0] = -1e30f; m_[mt][1] = -1e30f;
        l_[mt][0] = 0.f;    l_[mt][1] = 0.f;
#pragma unroll
        for (int ni = 0; ni < 8; ni++)
#pragma unroll
            for (int t = 0; t < 4; t++) o[mt][ni][t] = 0.f;
    }

    const int nT = SEQ / 64;
    for (int kt = 0; kt < nT; kt++) {
        asm volatile("cp.async.wait_group 1;");
        __syncthreads();

        const uint32_t ksb = sptr(stage + (kt & 1) * FKV);
        const uint32_t vtb = ksb + 4096 * 4;

        // ---- S = Q K^T for both m-tiles (K frags loaded once) ----
        float s[2][8][4];
#pragma unroll
        for (int mt = 0; mt < 2; mt++)
#pragma unroll
            for (int ni = 0; ni < 8; ni++)
#pragma unroll
                for (int t = 0; t < 4; t++) s[mt][ni][t] = 0.f;
#pragma unroll
        for (int ks = 0; ks < 8; ks++) {
            unsigned kbf[16];
#pragma unroll
            for (int gi = 0; gi < 4; gi++)
                ldsm4(&kbf[gi * 4], ksb + (kb_base[gi] ^ (uint32_t)(ks << 5)));
#pragma unroll
            for (int ni = 0; ni < 8; ni++) {
                mma8(s[0][ni], qf[0][ks], &kbf[ni * 2]);
                mma8(s[1][ni], qf[1][ks], &kbf[ni * 2]);
            }
        }

        // ---- online softmax per m-tile ----
#pragma unroll
        for (int mt = 0; mt < 2; mt++) {
            float rm0 = -1e30f, rm1 = -1e30f;
#pragma unroll
            for (int ni = 0; ni < 8; ni++) {
                rm0 = fmaxf(rm0, fmaxf(s[mt][ni][0], s[mt][ni][1]));
                rm1 = fmaxf(rm1, fmaxf(s[mt][ni][2], s[mt][ni][3]));
            }
            rm0 = fmaxf(rm0, __shfl_xor_sync(0xffffffffu, rm0, 1));
            rm0 = fmaxf(rm0, __shfl_xor_sync(0xffffffffu, rm0, 2));
            rm1 = fmaxf(rm1, __shfl_xor_sync(0xffffffffu, rm1, 1));
            rm1 = fmaxf(rm1, __shfl_xor_sync(0xffffffffu, rm1, 2));
            float mn0 = fmaxf(m_[mt][0], rm0), mn1 = fmaxf(m_[mt][1], rm1);

            float ps0 = 0.f, ps1 = 0.f;
#pragma unroll
            for (int ni = 0; ni < 8; ni++) {
                s[mt][ni][0] = ex2(s[mt][ni][0] - mn0);
                s[mt][ni][1] = ex2(s[mt][ni][1] - mn0);
                s[mt][ni][2] = ex2(s[mt][ni][2] - mn1);
                s[mt][ni][3] = ex2(s[mt][ni][3] - mn1);
                ps0 += s[mt][ni][0] + s[mt][ni][1];
                ps1 += s[mt][ni][2] + s[mt][ni][3];
            }
            ps0 += __shfl_xor_sync(0xffffffffu, ps0, 1);
            ps0 += __shfl_xor_sync(0xffffffffu, ps0, 2);
            ps1 += __shfl_xor_sync(0xffffffffu, ps1, 1);
            ps1 += __shfl_xor_sync(0xffffffffu, ps1, 2);

            float al0 = ex2(m_[mt][0] - mn0), al1 = ex2(m_[mt][1] - mn1);
            m_[mt][0] = mn0; m_[mt][1] = mn1;
            l_[mt][0] = l_[mt][0] * al0 + ps0;
            l_[mt][1] = l_[mt][1] * al1 + ps1;
#pragma unroll
            for (int ni = 0; ni < 8; ni++) {
                o[mt][ni][0] *= al0; o[mt][ni][1] *= al0;
                o[mt][ni][2] *= al1; o[mt][ni][3] *= al1;
            }
        }

        // ---- store P (tf32-rounded) for both m-tiles ----
        {
            const int sw = g << 2;
#pragma unroll
            for (int mt = 0; mt < 2; mt++)
#pragma unroll
                for (int ni = 0; ni < 8; ni++) {
                    const int colb = ni * 8 + 2 * c;
                    *(float2*)&Pw[(mt * 16 + g) * 64 + (colb ^ sw)] =
                        make_float2(tf32f(s[mt][ni][0]), tf32f(s[mt][ni][1]));
                    *(float2*)&Pw[(mt * 16 + g + 8) * 64 + (colb ^ sw)] =
                        make_float2(tf32f(s[mt][ni][2]), tf32f(s[mt][ni][3]));
                }
        }
        __syncwarp();

        // ---- O += P @ V : V frags shared across both m-tiles ----
#pragma unroll
        for (int ks = 0; ks < 8; ks++) {
            unsigned pa0[4], pa1[4];
            const uint32_t pofs = ((((uint32_t)ks << 5) | p_hi) ^ p_rsw);
            ldsm4(pa0, pwb + p_row + pofs);
            ldsm4(pa1, pwb + 4096 + p_row + pofs);
            const uint32_t xo = ((uint32_t)ks << 5) ^ vlc;
#pragma unroll
            for (int gi = 0; gi < 4; gi++) {
                unsigned vv[4];
                ldsm4(vv, vtb + vrow[gi] + xo);
                mma8b(o[0][2 * gi],     pa0, vv[0], vv[2]);
                mma8b(o[0][2 * gi + 1], pa0, vv[1], vv[3]);
                mma8b(o[1][2 * gi],     pa1, vv[0], vv[2]);
                mma8b(o[1][2 * gi + 1], pa1, vv[1], vv[3]);
            }
        }

        __syncthreads();
        if (kt + 2 < nT) issueKV(kt + 2);
        cpa_commit();
    }

    // ---- epilogue -> O raw fp32 (proj GEMM cvt's in-kernel) ----
#pragma unroll
    for (int mt = 0; mt < 2; mt++) {
        float inv0 = 1.f / l_[mt][0], inv1 = 1.f / l_[mt][1];
        int row0 = qt * 128 + wm + mt * 16 + g;
#pragma unroll
        for (int ni = 0; ni < 8; ni++) {
            int col = h * HD + ni * 8 + 2 * c;
            float* p0 = O + ((size_t)b * SEQ + row0) * DIM + col;
            float* p1 = O + ((size_t)b * SEQ + row0 + 8) * DIM + col;
            p0[0] = o[mt][ni][0] * inv0;
            p0[1] = o[mt][ni][1] * inv0;
            p1[0] = o[mt][ni][2] * inv1;
            p1[1] = o[mt][ni][3] * inv1;
        }
    }
}

// ---------------------------------------------------------------------------
extern "C" void kernel_launch(void* const* d_in, const int* in_sizes, int n_in,
                              void* d_out, int out_size) {
    const float* x        = (const float*)d_in[0];
    const float* context  = (const float*)d_in[1];
    const float* q_w      = (const float*)d_in[2];
    const float* kv_w     = (const float*)d_in[3];
    const float* qn_scale = (const float*)d_in[4];
    const float* qn_bias  = (const float*)d_in[5];
    const float* kn_scale = (const float*)d_in[6];
    const float* kn_bias  = (const float*)d_in[7];
    const float* proj_w   = (const float*)d_in[8];
    const float* proj_b   = (const float*)d_in[9];
    float* out = (float*)d_out;

    float *Qbuf, *KVbuf, *Q, *K, *V, *O, *qwt, *kvwt, *pwt;
    cudaGetSymbolAddress((void**)&Qbuf,  g_Qbuf);
    cudaGetSymbolAddress((void**)&KVbuf, g_KVbuf);
    cudaGetSymbolAddress((void**)&Q,     g_Q);
    cudaGetSymbolAddress((void**)&K,     g_K);
    cudaGetSymbolAddress((void**)&V,     g_V);
    cudaGetSymbolAddress((void**)&O,     g_O);
    cudaGetSymbolAddress((void**)&qwt,   g_qwt);
    cudaGetSymbolAddress((void**)&kvwt,  g_kvwt);
    cudaGetSymbolAddress((void**)&pwt,   g_pwt);

    cudaFuncSetAttribute(gemm_qkv,
        cudaFuncAttributeMaxDynamicSharedMemorySize, GEMM_SMEM);
    cudaFuncSetAttribute(gemm_tf32,
        cudaFuncAttributeMaxDynamicSharedMemorySize, GEMM_SMEM);
    cudaFuncSetAttribute(flash_tf32,
        cudaFuncAttributeMaxDynamicSharedMemorySize, FLASH_SMEM);

    // L1: prep (transpose+round weights only)
    prep_kernel<<<dim3(2048, 1, 3), 256>>>(q_w, proj_w, kv_w, qwt, pwt, kvwt);
    // L2: fused q + kv projections (A cvt'd in-kernel)
    gemm_qkv<<<dim3(24, 64), 256, GEMM_SMEM>>>(x, context, qwt, kvwt, Qbuf, KVbuf);
    // L3: fused LN (q: LN+RoPE, kv: LN k + V^T)
    ln_all_kernel<<<dim3(32, 16, 8), 256>>>(
        Qbuf, KVbuf, qn_scale, qn_bias, kn_scale, kn_bias, Q, K, V);
    // L4: attention (profiled slot)
    flash_tf32<<<dim3(SEQ / 128, NHEAD, BATCH), 128, FLASH_SMEM>>>(Q, K, V, O);
    // L5: out = O @ proj_w + proj_b
    gemm_tf32<<<dim3(8, 64), 256, GEMM_SMEM>>>(O, pwt, proj_b, out, DIM, DIM);
}

// round 15
// speedup vs baseline: 1.0327x; 1.0327x over previous
#include <cuda_runtime.h>
#include <math.h>
#include <stdint.h>

#define BATCH 4
#define SEQ   2048
#define DIM   1024
#define NHEAD 16
#define HD    64
#define ROWS  (BATCH*SEQ)   // 8192

// ---------------- scratch (device globals; no allocation allowed) ----------
__device__ float g_Qbuf[(size_t)ROWS * DIM];
__device__ float g_KVbuf[(size_t)ROWS * 2 * DIM];
__device__ float g_Q[(size_t)ROWS * DIM];           // [B,H,S,Hd] tf32
__device__ float g_K[(size_t)ROWS * DIM];           // [B,H,Sc,Hd] tf32
__device__ float g_V[(size_t)ROWS * DIM];           // [B,H,Hd,Sc] transposed tf32
__device__ float g_O[(size_t)ROWS * DIM];           // [B,S,H*Hd] tf32
__device__ float g_xc[(size_t)ROWS * DIM];          // tf32 x
__device__ float g_cc[(size_t)ROWS * DIM];          // tf32 context
__device__ float g_qwt[(size_t)DIM * DIM];          // q_w^T   [N][K] tf32
__device__ float g_kvwt[(size_t)2 * DIM * DIM];     // kv_w^T  [2N][K] tf32
__device__ float g_pwt[(size_t)DIM * DIM];          // proj_w^T tf32

// ---------------- helpers ---------------------------------------------------
__device__ __forceinline__ unsigned tf32(float x) {
    unsigned u;
    asm("cvt.rna.tf32.f32 %0, %1;" : "=r"(u) : "f"(x));
    return u;
}
__device__ __forceinline__ float tf32f(float x) { return __uint_as_float(tf32(x)); }
__device__ __forceinline__ float ex2(float x) {
    float y;
    asm("ex2.approx.f32 %0, %1;" : "=f"(y) : "f"(x));
    return y;
}

__device__ __forceinline__ void mma8(float* d, const unsigned* a, const unsigned* b) {
    asm volatile(
        "mma.sync.aligned.m16n8k8.row.col.f32.tf32.tf32.f32 "
        "{%0,%1,%2,%3}, {%4,%5,%6,%7}, {%8,%9}, {%0,%1,%2,%3};"
        : "+f"(d[0]), "+f"(d[1]), "+f"(d[2]), "+f"(d[3])
        : "r"(a[0]), "r"(a[1]), "r"(a[2]), "r"(a[3]), "r"(b[0]), "r"(b[1]));
}
__device__ __forceinline__ void mma8b(float* d, const unsigned* a,
                                      unsigned b0, unsigned b1) {
    asm volatile(
        "mma.sync.aligned.m16n8k8.row.col.f32.tf32.tf32.f32 "
        "{%0,%1,%2,%3}, {%4,%5,%6,%7}, {%8,%9}, {%0,%1,%2,%3};"
        : "+f"(d[0]), "+f"(d[1]), "+f"(d[2]), "+f"(d[3])
        : "r"(a[0]), "r"(a[1]), "r"(a[2]), "r"(a[3]), "r"(b0), "r"(b1));
}
__device__ __forceinline__ void ldsm4(unsigned* r, uint32_t addr) {
    asm volatile("ldmatrix.sync.aligned.m8n8.x4.shared.b16 {%0,%1,%2,%3}, [%4];"
        : "=r"(r[0]), "=r"(r[1]), "=r"(r[2]), "=r"(r[3]) : "r"(addr));
}
__device__ __forceinline__ void cpa16(uint32_t s, const void* g) {
    asm volatile("cp.async.cg.shared.global [%0], [%1], 16;" :: "r"(s), "l"(g));
}
__device__ __forceinline__ void cpa_commit() {
    asm volatile("cp.async.commit_group;");
}
__device__ __forceinline__ uint32_t sptr(const void* p) {
    return (uint32_t)__cvta_generic_to_shared(p);
}

// ---------------- prep: round x/context + transpose-round 3 weights --------
__global__ void prep_kernel(
        const float4* __restrict__ x,  const float4* __restrict__ cc,
        const float* __restrict__ qw,  const float* __restrict__ pw,
        const float* __restrict__ kvw,
        float4* __restrict__ xo, float4* __restrict__ cco,
        float* __restrict__ qwt, float* __restrict__ pwt,
        float* __restrict__ kvwt) {
    const int z = blockIdx.z;
    if (z < 2) {
        const float4* src = z ? cc : x;
        float4* dst = z ? cco : xo;
        const int n4 = ROWS * DIM / 4;
        for (int i = blockIdx.x * blockDim.x + threadIdx.x; i < n4;
             i += gridDim.x * blockDim.x) {
            float4 v = src[i];
            v.x = tf32f(v.x); v.y = tf32f(v.y);
            v.z = tf32f(v.z); v.w = tf32f(v.w);
            dst[i] = v;
        }
        return;
    }
    const float* W; float* Wt; int N;
    if (z == 2)      { W = qw;  Wt = qwt;  N = DIM; }
    else if (z == 3) { W = pw;  Wt = pwt;  N = DIM; }
    else             { W = kvw; Wt = kvwt; N = 2 * DIM; }
    const int ntx = N / 32;
    const int tile = blockIdx.x;
    if (tile >= (DIM / 32) * ntx) return;
    const int kx = (tile / ntx) * 32, ny = (tile % ntx) * 32;
    __shared__ float t[32][33];
    const int tx = threadIdx.x & 31, ty = threadIdx.x >> 5;
#pragma unroll
    for (int j = 0; j < 32; j += 8)
        t[ty + j][tx] = tf32f(W[(size_t)(kx + ty + j) * N + ny + tx]);
    __syncthreads();
#pragma unroll
    for (int j = 0; j < 32; j += 8)
        Wt[(size_t)(ny + ty + j) * DIM + kx + tx] = t[tx][ty + j];
}

// ---------------- TF32 GEMM core (R10 config): C = A @ Bt^T (+bias) --------
// K-tile 16, 3-stage cp.async, prefetch issued mid-slab. 8 warps (2m x 4n).
#define TSTR 20
#define OP_SZ (128*TSTR)
#define STG_B (2*OP_SZ*4)
#define GEMM_SMEM (3*STG_B)            // 61440 B

__device__ __forceinline__ void gemm_core(
        const float* __restrict__ A, const float* __restrict__ Bt,
        const float* __restrict__ bias, float* __restrict__ C,
        int N, int K, float* sm, int bx, int by) {
    const int tid  = threadIdx.x;
    const int warp = tid >> 5, lane = tid & 31;
    const int g = lane >> 2, c = lane & 3;
    const int wm = (warp >> 2) * 64, wn = (warp & 3) * 32;
    const int bm = by * 128, bn = bx * 128;

    const int ar  = tid >> 2;
    const int ac4 = (tid & 3) << 2;

    const float* Ap = A  + (size_t)(bm + ar) * K + ac4;
    const float* Bp = Bt + (size_t)(bn + ar) * K + ac4;

    const uint32_t s0 = sptr(sm);
    const uint32_t cpA0 = s0 + (ar * TSTR + ac4) * 4;
    const uint32_t cpA1 = cpA0 + 64 * TSTR * 4;
    const uint32_t cpB0 = cpA0 + OP_SZ * 4;
    const uint32_t cpB1 = cpB0 + 64 * TSTR * 4;

    const int mloc = lane >> 3, rw = lane & 7;
    const uint32_t ard = s0 +
        ((wm + ((mloc & 1) << 3) + rw) * TSTR + ((mloc >> 1) << 2)) * 4;
    const uint32_t brd = s0 + OP_SZ * 4 +
        ((wn + ((lane >> 4) << 3) + rw) * TSTR + (((lane >> 3) & 1) << 2)) * 4;

    float acc[4][4][4];
#pragma unroll
    for (int mi = 0; mi < 4; mi++)
#pragma unroll
        for (int ni = 0; ni < 4; ni++)
#pragma unroll
            for (int t = 0; t < 4; t++) acc[mi][ni][t] = 0.f;

    const int nT = K >> 4;
    auto issue = [&](int t) {
        const uint32_t off = (uint32_t)(t % 3) * STG_B;
        const int k0 = t << 4;
        cpa16(cpA0 + off, Ap + k0);
        cpa16(cpA1 + off, Ap + (size_t)64 * K + k0);
        cpa16(cpB0 + off, Bp + k0);
        cpa16(cpB1 + off, Bp + (size_t)64 * K + k0);
    };

    issue(0); cpa_commit();
    issue(1); cpa_commit();

    for (int t = 0; t < nT; t++) {
        asm volatile("cp.async.wait_group 1;");
        __syncthreads();

        const uint32_t off = (uint32_t)(t % 3) * STG_B;

        {
            unsigned af[4][4], bfr[8];
#pragma unroll
            for (int mi = 0; mi < 4; mi++)
                ldsm4(af[mi], ard + off + mi * (16 * TSTR * 4));
            ldsm4(bfr,     brd + off);
            ldsm4(bfr + 4, brd + off + 16 * TSTR * 4);
#pragma unroll
            for (int mi = 0; mi < 4; mi++)
#pragma unroll
                for (int ni = 0; ni < 4; ni++)
                    mma8b(acc[mi][ni], af[mi], bfr[2 * ni], bfr[2 * ni + 1]);
        }

        if (t + 2 < nT) issue(t + 2);
        cpa_commit();

        {
            unsigned af[4][4], bfr[8];
#pragma unroll
            for (int mi = 0; mi < 4; mi++)
                ldsm4(af[mi], ard + off + mi * (16 * TSTR * 4) + 32);
            ldsm4(bfr,     brd + off + 32);
            ldsm4(bfr + 4, brd + off + 16 * TSTR * 4 + 32);
#pragma unroll
            for (int mi = 0; mi < 4; mi++)
#pragma unroll
                for (int ni = 0; ni < 4; ni++)
                    mma8b(acc[mi][ni], af[mi], bfr[2 * ni], bfr[2 * ni + 1]);
        }
    }

#pragma unroll
    for (int mi = 0; mi < 4; mi++) {
        int row = bm + wm + mi * 16 + g;
#pragma unroll
        for (int ni = 0; ni < 4; ni++) {
            int col = bn + wn + ni * 8 + 2 * c;
            float bv0 = bias ? bias[col] : 0.f;
            float bv1 = bias ? bias[col + 1] : 0.f;
            float* p0 = C + (size_t)row * N + col;
            float* p1 = C + (size_t)(row + 8) * N + col;
            p0[0] = acc[mi][ni][0] + bv0; p0[1] = acc[mi][ni][1] + bv1;
            p1[0] = acc[mi][ni][2] + bv0; p1[1] = acc[mi][ni][3] + bv1;
        }
    }
}

// fused q+kv projections: bx<8 -> q (N=1024), bx>=8 -> kv (N=2048)
__global__ __launch_bounds__(256) void gemm_qkv(
        const float* __restrict__ Ax, const float* __restrict__ Ac,
        const float* __restrict__ Bq, const float* __restrict__ Bkv,
        float* __restrict__ Cq, float* __restrict__ Ckv) {
    extern __shared__ float sm[];
    if (blockIdx.x < 8)
        gemm_core(Ax, Bq, nullptr, Cq, DIM, DIM, sm, blockIdx.x, blockIdx.y);
    else
        gemm_core(Ac, Bkv, nullptr, Ckv, 2 * DIM, DIM, sm,
                  blockIdx.x - 8, blockIdx.y);
}

__global__ __launch_bounds__(256) void gemm_tf32(
        const float* __restrict__ A, const float* __restrict__ Bt,
        const float* __restrict__ bias, float* __restrict__ C,
        int N, int K) {
    extern __shared__ float sm[];
    gemm_core(A, Bt, bias, C, N, K, sm, blockIdx.x, blockIdx.y);
}

// ---------------- fused LN: q-mode (LN+RoPE) and kv-mode (LN k + V^T) ------
__global__ __launch_bounds__(256) void ln_all_kernel(
        const float* __restrict__ Qbuf, const float* __restrict__ KVbuf,
        const float* __restrict__ qg, const float* __restrict__ qb,
        const float* __restrict__ kg, const float* __restrict__ kb_,
        float* __restrict__ Q, float* __restrict__ K, float* __restrict__ Vt) {
    const int h = blockIdx.y, rb = blockIdx.x * 64;
    const int tid = threadIdx.x, warp = tid >> 5, lane = tid & 31;

    if (blockIdx.z >= 4) {
        const int b = blockIdx.z - 4;
        const float ga0 = qg[lane], ga1 = qg[lane + 32];
        const float be0 = qb[lane], be1 = qb[lane + 32];
        const float invf = ex2(-(float)lane * (13.28771237954945f / 32.f));
#pragma unroll
        for (int j = 0; j < 8; j++) {
            const int s = rb + warp * 8 + j;
            const float* in = Qbuf + ((size_t)b * SEQ + s) * DIM + h * HD;
            float v0 = in[lane], v1 = in[lane + 32];
            float sum = v0 + v1;
#pragma unroll
            for (int o = 16; o; o >>= 1) sum += __shfl_xor_sync(0xffffffffu, sum, o);
            float mu = sum * (1.f / 64.f);
            float d0 = v0 - mu, d1 = v1 - mu;
            float vs = d0 * d0 + d1 * d1;
#pragma unroll
            for (int o = 16; o; o >>= 1) vs += __shfl_xor_sync(0xffffffffu, vs, o);
            float rstd = rsqrtf(vs * (1.f / 64.f) + 1e-5f);
            float y0 = d0 * rstd * ga0 + be0;
            float y1 = d1 * rstd * ga1 + be1;
            float sn, cs;
            sincosf((float)s * invf, &sn, &cs);
            float* outp = Q + ((size_t)(b * NHEAD + h) * SEQ + s) * HD;
            outp[lane]      = tf32f(y0 * cs - y1 * sn);
            outp[lane + 32] = tf32f(y0 * sn + y1 * cs);
        }
        return;
    }

    __shared__ float Vs[64 * 65];
    const int b = blockIdx.z;
    const float ga0 = kg[lane], ga1 = kg[lane + 32];
    const float be0 = kb_[lane], be1 = kb_[lane + 32];
#pragma unroll
    for (int j = 0; j < 8; j++) {
        const int kl  = warp * 8 + j;
        const int key = rb + kl;
        const float* kin = KVbuf + ((size_t)b * SEQ + key) * (2 * DIM) + h * HD;
        const float* vin = kin + DIM;
        float v0 = kin[lane], v1 = kin[lane + 32];
        float sum = v0 + v1;
#pragma unroll
        for (int o = 16; o; o >>= 1) sum += __shfl_xor_sync(0xffffffffu, sum, o);
        float mu = sum * (1.f / 64.f);
        float d0 = v0 - mu, d1 = v1 - mu;
        float vs = d0 * d0 + d1 * d1;
#pragma unroll
        for (int o = 16; o; o >>= 1) vs += __shfl_xor_sync(0xffffffffu, vs, o);
        float rstd = rsqrtf(vs * (1.f / 64.f) + 1e-5f);
        size_t ob = ((size_t)(b * NHEAD + h) * SEQ + key) * HD;
        K[ob + lane]      = tf32f(d0 * rstd * ga0 + be0);
        K[ob + lane + 32] = tf32f(d1 * rstd * ga1 + be1);
        Vs[lane * 65 + kl]        = tf32f(vin[lane]);
        Vs[(lane + 32) * 65 + kl] = tf32f(vin[lane + 32]);
    }
    __syncthreads();
    const int d = tid >> 2, c0 = (tid & 3) * 16;
    float* dst = Vt + ((size_t)((b * NHEAD + h) * HD + d)) * SEQ + rb + c0;
#pragma unroll
    for (int e = 0; e < 16; e += 4) {
        const float* s = &Vs[d * 65 + c0 + e];
        *(float4*)(dst + e) = make_float4(s[0], s[1], s[2], s[3]);
    }
}

// --------- flash attention: 128q x 64k, 4 warps x 32 rows (R12 form) -------
#define QIDX(r, col) ((r) * 64 + ((col) ^ (((r) & 7) << 2)))
#define VTIDX(d, key) ((d) * 64 + (((((key) >> 2) ^ ((d) & 7)) << 2) | ((key) & 3)))
#define FKV 8192
#define PWARP 2048
#define FLASH_SMEM ((2*FKV + 4*PWARP)*4)    // 98304 B

#define QSCALE (0.125f * 1.44269504088896340736f)

__global__ __launch_bounds__(128, 2) void flash_tf32(
        const float* __restrict__ Q, const float* __restrict__ K,
        const float* __restrict__ Vt, float* __restrict__ O) {
    extern __shared__ float stage[];

    const int qt = blockIdx.x, h = blockIdx.y, b = blockIdx.z;
    const int tid  = threadIdx.x;
    const int warp = tid >> 5, lane = tid & 31;
    const int g = lane >> 2, c = lane & 3;
    const int wm = warp * 32;

    const int mloc = lane >> 3, rw = lane & 7;
    uint32_t kb_base[4];
#pragma unroll
    for (int gi = 0; gi < 4; gi++) {
        int row = (gi * 2 + (mloc >> 1)) * 8 + rw;
        kb_base[gi] = (uint32_t)(row * 256) + ((((mloc & 1) << 4) ^ (rw << 4)));
    }
    const int Lr = lane & 15, h4 = lane >> 4, mmv = lane & 7;
    uint32_t vrow[4];
#pragma unroll
    for (int gi = 0; gi < 4; gi++) vrow[gi] = (uint32_t)((16 * gi + Lr) * 256);
    const uint32_t vlc = ((uint32_t)h4 << 4) ^ ((uint32_t)mmv << 4);
    float* Pw = stage + 2 * FKV + warp * PWARP;
    const uint32_t pwb = sptr(Pw);
    const uint32_t p_row = (uint32_t)((((lane >> 3) & 1) * 8 + rw) * 256);
    const uint32_t p_hi  = (uint32_t)((lane >> 4) << 4);
    const uint32_t p_rsw = (uint32_t)(rw << 4);

    const float* Qg  = Q  + ((size_t)(b * NHEAD + h) * SEQ + qt * 128) * HD;
    const float* Kg  = K  + (size_t)(b * NHEAD + h) * SEQ * HD;
    const float* Vtg = Vt + (size_t)(b * NHEAD + h) * HD * SEQ;

#pragma unroll
    for (int j = 0; j < 16; j++) {
        int i = tid + j * 128;
        int r = i >> 4, c4 = (i & 15) << 2;
        float* dst = (r < 64) ? &stage[QIDX(r, c4)] : &stage[4096 + QIDX(r - 64, c4)];
        cpa16(sptr(dst), Qg + (size_t)r * 64 + c4);
    }
    cpa_commit();
    asm volatile("cp.async.wait_group 0;");
    __syncthreads();

    unsigned qf[2][8][4];
#pragma unroll
    for (int mt = 0; mt < 2; mt++) {
        const int rbase = wm + mt * 16;
        const float* buf = (rbase < 64) ? stage : stage + 4096;
        const int rb = rbase & 63;
#pragma unroll
        for (int ks = 0; ks < 8; ks++) {
            int kk = ks * 8 + c;
            qf[mt][ks][0] = tf32(QSCALE * buf[QIDX(rb + g, kk)]);
            qf[mt][ks][1] = tf32(QSCALE * buf[QIDX(rb + 8 + g, kk)]);
            qf[mt][ks][2] = tf32(QSCALE * buf[QIDX(rb + g, kk + 4)]);
            qf[mt][ks][3] = tf32(QSCALE * buf[QIDX(rb + 8 + g, kk + 4)]);
        }
    }
    __syncthreads();

    auto issueKV = [&](int t) {
        float* Kb = stage + (t & 1) * FKV;
        float* Vb = Kb + 4096;
#pragma unroll
        for (int j = 0; j < 8; j++) {
            int i = tid + j * 128;
            int r = i >> 4, c4 = (i & 15) << 2;
            cpa16(sptr(&Kb[QIDX(r, c4)]), Kg + (size_t)(t * 64 + r) * 64 + c4);
            cpa16(sptr(&Vb[VTIDX(r, c4)]), Vtg + (size_t)r * SEQ + t * 64 + c4);
        }
    };

    issueKV(0); cpa_commit();
    issueKV(1); cpa_commit();

    float m_[2][2], l_[2][2], o[2][8][4];
#pragma unroll
    for (int mt = 0; mt < 2; mt++) {
        m_[mt][0] = -1e30f; m_[mt][1] = -1e30f;
        l_[mt][0] = 0.f;    l_[mt][1] = 0.f;
#pragma unroll
        for (int ni = 0; ni < 8; ni++)
#pragma unroll
            for (int t = 0; t < 4; t++) o[mt][ni][t] = 0.f;
    }

    const int nT = SEQ / 64;
    for (int kt = 0; kt < nT; kt++) {
        asm volatile("cp.async.wait_group 1;");
        __syncthreads();

        const uint32_t ksb = sptr(stage + (kt & 1) * FKV);
        const uint32_t vtb = ksb + 4096 * 4;

        // ---- S = Q K^T for both m-tiles (K frags loaded once) ----
        float s[2][8][4];
#pragma unroll
        for (int mt = 0; mt < 2; mt++)
#pragma unroll
            for (int ni = 0; ni < 8; ni++)
#pragma unroll
                for (int t = 0; t < 4; t++) s[mt][ni][t] = 0.f;
#pragma unroll
        for (int ks = 0; ks < 8; ks++) {
            unsigned kbf[16];
#pragma unroll
            for (int gi = 0; gi < 4; gi++)
                ldsm4(&kbf[gi * 4], ksb + (kb_base[gi] ^ (uint32_t)(ks << 5)));
#pragma unroll
            for (int ni = 0; ni < 8; ni++) {
                mma8(s[0][ni], qf[0][ks], &kbf[ni * 2]);
                mma8(s[1][ni], qf[1][ks], &kbf[ni * 2]);
            }
        }

        // ---- online softmax per m-tile ----
#pragma unroll
        for (int mt = 0; mt < 2; mt++) {
            float rm0 = -1e30f, rm1 = -1e30f;
#pragma unroll
            for (int ni = 0; ni < 8; ni++) {
                rm0 = fmaxf(rm0, fmaxf(s[mt][ni][0], s[mt][ni][1]));
                rm1 = fmaxf(rm1, fmaxf(s[mt][ni][2], s[mt][ni][3]));
            }
            rm0 = fmaxf(rm0, __shfl_xor_sync(0xffffffffu, rm0, 1));
            rm0 = fmaxf(rm0, __shfl_xor_sync(0xffffffffu, rm0, 2));
            rm1 = fmaxf(rm1, __shfl_xor_sync(0xffffffffu, rm1, 1));
            rm1 = fmaxf(rm1, __shfl_xor_sync(0xffffffffu, rm1, 2));
            float mn0 = fmaxf(m_[mt][0], rm0), mn1 = fmaxf(m_[mt][1], rm1);

            float ps0 = 0.f, ps1 = 0.f;
#pragma unroll
            for (int ni = 0; ni < 8; ni++) {
                s[mt][ni][0] = ex2(s[mt][ni][0] - mn0);
                s[mt][ni][1] = ex2(s[mt][ni][1] - mn0);
                s[mt][ni][2] = ex2(s[mt][ni][2] - mn1);
                s[mt][ni][3] = ex2(s[mt][ni][3] - mn1);
                ps0 += s[mt][ni][0] + s[mt][ni][1];
                ps1 += s[mt][ni][2] + s[mt][ni][3];
            }
            ps0 += __shfl_xor_sync(0xffffffffu, ps0, 1);
            ps0 += __shfl_xor_sync(0xffffffffu, ps0, 2);
            ps1 += __shfl_xor_sync(0xffffffffu, ps1, 1);
            ps1 += __shfl_xor_sync(0xffffffffu, ps1, 2);

            float al0 = ex2(m_[mt][0] - mn0), al1 = ex2(m_[mt][1] - mn1);
            m_[mt][0] = mn0; m_[mt][1] = mn1;
            l_[mt][0] = l_[mt][0] * al0 + ps0;
            l_[mt][1] = l_[mt][1] * al1 + ps1;
#pragma unroll
            for (int ni = 0; ni < 8; ni++) {
                o[mt][ni][0] *= al0; o[mt][ni][1] *= al0;
                o[mt][ni][2] *= al1; o[mt][ni][3] *= al1;
            }
        }

        // ---- store P (tf32-rounded) for both m-tiles ----
        {
            const int sw = g << 2;
#pragma unroll
            for (int mt = 0; mt < 2; mt++)
#pragma unroll
                for (int ni = 0; ni < 8; ni++) {
                    const int colb = ni * 8 + 2 * c;
                    *(float2*)&Pw[(mt * 16 + g) * 64 + (colb ^ sw)] =
                        make_float2(tf32f(s[mt][ni][0]), tf32f(s[mt][ni][1]));
                    *(float2*)&Pw[(mt * 16 + g + 8) * 64 + (colb ^ sw)] =
                        make_float2(tf32f(s[mt][ni][2]), tf32f(s[mt][ni][3]));
                }
        }
        __syncwarp();

        // ---- O += P @ V : V frags shared across both m-tiles ----
#pragma unroll
        for (int ks = 0; ks < 8; ks++) {
            unsigned pa0[4], pa1[4];
            const uint32_t pofs = ((((uint32_t)ks << 5) | p_hi) ^ p_rsw);
            ldsm4(pa0, pwb + p_row + pofs);
            ldsm4(pa1, pwb + 4096 + p_row + pofs);
            const uint32_t xo = ((uint32_t)ks << 5) ^ vlc;
#pragma unroll
            for (int gi = 0; gi < 4; gi++) {
                unsigned vv[4];
                ldsm4(vv, vtb + vrow[gi] + xo);
                mma8b(o[0][2 * gi],     pa0, vv[0], vv[2]);
                mma8b(o[0][2 * gi + 1], pa0, vv[1], vv[3]);
                mma8b(o[1][2 * gi],     pa1, vv[0], vv[2]);
                mma8b(o[1][2 * gi + 1], pa1, vv[1], vv[3]);
            }
        }

        __syncthreads();
        if (kt + 2 < nT) issueKV(kt + 2);
        cpa_commit();
    }

    // ---- epilogue -> O [B, S, H*Hd], tf32-rounded ----
#pragma unroll
    for (int mt = 0; mt < 2; mt++) {
        float inv0 = 1.f / l_[mt][0], inv1 = 1.f / l_[mt][1];
        int row0 = qt * 128 + wm + mt * 16 + g;
#pragma unroll
        for (int ni = 0; ni < 8; ni++) {
            int col = h * HD + ni * 8 + 2 * c;
            float* p0 = O + ((size_t)b * SEQ + row0) * DIM + col;
            float* p1 = O + ((size_t)b * SEQ + row0 + 8) * DIM + col;
            p0[0] = tf32f(o[mt][ni][0] * inv0);
            p0[1] = tf32f(o[mt][ni][1] * inv0);
            p1[0] = tf32f(o[mt][ni][2] * inv1);
            p1[1] = tf32f(o[mt][ni][3] * inv1);
        }
    }
}

// ---------------------------------------------------------------------------
extern "C" void kernel_launch(void* const* d_in, const int* in_sizes, int n_in,
                              void* d_out, int out_size) {
    const float* x        = (const float*)d_in[0];
    const float* context  = (const float*)d_in[1];
    const float* q_w      = (const float*)d_in[2];
    const float* kv_w     = (const float*)d_in[3];
    const float* qn_scale = (const float*)d_in[4];
    const float* qn_bias  = (const float*)d_in[5];
    const float* kn_scale = (const float*)d_in[6];
    const float* kn_bias  = (const float*)d_in[7];
    const float* proj_w   = (const float*)d_in[8];
    const float* proj_b   = (const float*)d_in[9];
    float* out = (float*)d_out;

    float *Qbuf, *KVbuf, *Q, *K, *V, *O, *xc, *cc, *qwt, *kvwt, *pwt;
    cudaGetSymbolAddress((void**)&Qbuf,  g_Qbuf);
    cudaGetSymbolAddress((void**)&KVbuf, g_KVbuf);
    cudaGetSymbolAddress((void**)&Q,     g_Q);
    cudaGetSymbolAddress((void**)&K,     g_K);
    cudaGetSymbolAddress((void**)&V,     g_V);
    cudaGetSymbolAddress((void**)&O,     g_O);
    cudaGetSymbolAddress((void**)&xc,    g_xc);
    cudaGetSymbolAddress((void**)&cc,    g_cc);
    cudaGetSymbolAddress((void**)&qwt,   g_qwt);
    cudaGetSymbolAddress((void**)&kvwt,  g_kvwt);
    cudaGetSymbolAddress((void**)&pwt,   g_pwt);

    cudaFuncSetAttribute(gemm_qkv,
        cudaFuncAttributeMaxDynamicSharedMemorySize, GEMM_SMEM);
    cudaFuncSetAttribute(gemm_tf32,
        cudaFuncAttributeMaxDynamicSharedMemorySize, GEMM_SMEM);
    cudaFuncSetAttribute(flash_tf32,
        cudaFuncAttributeMaxDynamicSharedMemorySize, FLASH_SMEM);

    // L1: prep (round x/context; transpose+round weights)
    prep_kernel<<<dim3(2048, 1, 5), 256>>>(
        (const float4*)x, (const float4*)context, q_w, proj_w, kv_w,
        (float4*)xc, (float4*)cc, qwt, pwt, kvwt);
    // L2: fused q + kv projections (no dead CTAs)
    gemm_qkv<<<dim3(24, 64), 256, GEMM_SMEM>>>(xc, cc, qwt, kvwt, Qbuf, KVbuf);
    // L3: fused LN (q: LN+RoPE, kv: LN k + V^T)
    ln_all_kernel<<<dim3(32, 16, 8), 256>>>(
        Qbuf, KVbuf, qn_scale, qn_bias, kn_scale, kn_bias, Q, K, V);
    // L4: attention (profiled slot)
    flash_tf32<<<dim3(SEQ / 128, NHEAD, BATCH), 128, FLASH_SMEM>>>(Q, K, V, O);
    // L5: out = O @ proj_w + proj_b
    gemm_tf32<<<dim3(8, 64), 256, GEMM_SMEM>>>(O, pwt, proj_b, out, DIM, DIM);
}

// round 16
// speedup vs baseline: 1.0787x; 1.0445x over previous
#include <cuda_runtime.h>
#include <math.h>
#include <stdint.h>

#define BATCH 4
#define SEQ   2048
#define DIM   1024
#define NHEAD 16
#define HD    64
#define ROWS  (BATCH*SEQ)   // 8192

// ---------------- scratch (device globals; no allocation allowed) ----------
__device__ float g_Qbuf[(size_t)ROWS * DIM];
__device__ float g_KVbuf[(size_t)ROWS * 2 * DIM];
__device__ float g_Q[(size_t)ROWS * DIM];           // [B,H,S,Hd] tf32
__device__ float g_K[(size_t)ROWS * DIM];           // [B,H,Sc,Hd] tf32
__device__ float g_V[(size_t)ROWS * DIM];           // [B,H,Hd,Sc] transposed tf32
__device__ float g_O[(size_t)ROWS * DIM];           // [B,S,H*Hd] tf32
__device__ float g_xc[(size_t)ROWS * DIM];          // tf32 x
__device__ float g_cc[(size_t)ROWS * DIM];          // tf32 context
__device__ float g_qwt[(size_t)DIM * DIM];          // q_w^T   [N][K] tf32
__device__ float g_kvwt[(size_t)2 * DIM * DIM];     // kv_w^T  [2N][K] tf32
__device__ float g_pwt[(size_t)DIM * DIM];          // proj_w^T tf32

// ---------------- helpers ---------------------------------------------------
__device__ __forceinline__ unsigned tf32(float x) {
    unsigned u;
    asm("cvt.rna.tf32.f32 %0, %1;" : "=r"(u) : "f"(x));
    return u;
}
__device__ __forceinline__ float tf32f(float x) { return __uint_as_float(tf32(x)); }
__device__ __forceinline__ float ex2(float x) {
    float y;
    asm("ex2.approx.f32 %0, %1;" : "=f"(y) : "f"(x));
    return y;
}

__device__ __forceinline__ void mma8(float* d, const unsigned* a, const unsigned* b) {
    asm volatile(
        "mma.sync.aligned.m16n8k8.row.col.f32.tf32.tf32.f32 "
        "{%0,%1,%2,%3}, {%4,%5,%6,%7}, {%8,%9}, {%0,%1,%2,%3};"
        : "+f"(d[0]), "+f"(d[1]), "+f"(d[2]), "+f"(d[3])
        : "r"(a[0]), "r"(a[1]), "r"(a[2]), "r"(a[3]), "r"(b[0]), "r"(b[1]));
}
__device__ __forceinline__ void mma8b(float* d, const unsigned* a,
                                      unsigned b0, unsigned b1) {
    asm volatile(
        "mma.sync.aligned.m16n8k8.row.col.f32.tf32.tf32.f32 "
        "{%0,%1,%2,%3}, {%4,%5,%6,%7}, {%8,%9}, {%0,%1,%2,%3};"
        : "+f"(d[0]), "+f"(d[1]), "+f"(d[2]), "+f"(d[3])
        : "r"(a[0]), "r"(a[1]), "r"(a[2]), "r"(a[3]), "r"(b0), "r"(b1));
}
__device__ __forceinline__ void ldsm4(unsigned* r, uint32_t addr) {
    asm volatile("ldmatrix.sync.aligned.m8n8.x4.shared.b16 {%0,%1,%2,%3}, [%4];"
        : "=r"(r[0]), "=r"(r[1]), "=r"(r[2]), "=r"(r[3]) : "r"(addr));
}
__device__ __forceinline__ void cpa16(uint32_t s, const void* g) {
    asm volatile("cp.async.cg.shared.global [%0], [%1], 16;" :: "r"(s), "l"(g));
}
__device__ __forceinline__ void cpa_commit() {
    asm volatile("cp.async.commit_group;");
}
__device__ __forceinline__ uint32_t sptr(const void* p) {
    return (uint32_t)__cvta_generic_to_shared(p);
}

// ---------------- prep kernels (split for launch ordering) ------------------
__global__ void prep_w_kernel(
        const float* __restrict__ qw,  const float* __restrict__ pw,
        const float* __restrict__ kvw,
        float* __restrict__ qwt, float* __restrict__ pwt,
        float* __restrict__ kvwt) {
    const int z = blockIdx.z;
    const float* W; float* Wt; int N;
    if (z == 0)      { W = qw;  Wt = qwt;  N = DIM; }
    else if (z == 1) { W = pw;  Wt = pwt;  N = DIM; }
    else             { W = kvw; Wt = kvwt; N = 2 * DIM; }
    const int ntx = N / 32;
    const int tile = blockIdx.x;
    if (tile >= (DIM / 32) * ntx) return;
    const int kx = (tile / ntx) * 32, ny = (tile % ntx) * 32;
    __shared__ float t[32][33];
    const int tx = threadIdx.x & 31, ty = threadIdx.x >> 5;
#pragma unroll
    for (int j = 0; j < 32; j += 8)
        t[ty + j][tx] = tf32f(W[(size_t)(kx + ty + j) * N + ny + tx]);
    __syncthreads();
#pragma unroll
    for (int j = 0; j < 32; j += 8)
        Wt[(size_t)(ny + ty + j) * DIM + kx + tx] = t[tx][ty + j];
}

__global__ void round_kernel(const float4* __restrict__ in,
                             float4* __restrict__ out) {
    const int n4 = ROWS * DIM / 4;
    for (int i = blockIdx.x * blockDim.x + threadIdx.x; i < n4;
         i += gridDim.x * blockDim.x) {
        float4 v = in[i];
        v.x = tf32f(v.x); v.y = tf32f(v.y);
        v.z = tf32f(v.z); v.w = tf32f(v.w);
        out[i] = v;
    }
}

// ---------------- TF32 GEMM core: K-tile 32, 3-stage, mid-slab issue -------
#define TSTR 36
#define OP_SZ (128*TSTR)               // floats per operand per stage
#define STG_B (2*OP_SZ*4)              // 36864 B per stage
#define GEMM_SMEM (3*STG_B)            // 110592 B

__device__ __forceinline__ void gemm_core(
        const float* __restrict__ A, const float* __restrict__ Bt,
        const float* __restrict__ bias, float* __restrict__ C,
        int N, int K, float* sm, int bx, int by) {
    const int tid  = threadIdx.x;
    const int warp = tid >> 5, lane = tid & 31;
    const int g = lane >> 2, c = lane & 3;
    const int wm = (warp >> 2) * 64, wn = (warp & 3) * 32;
    const int bm = by * 128, bn = bx * 128;

    // cp.async mapping: row = tid>>3 (+32j), 16B chunk = tid&7
    const int ar = tid >> 3;
    const int c8 = tid & 7;

    const float* Ap = A  + (size_t)(bm + ar) * K + c8 * 4;
    const float* Bp = Bt + (size_t)(bn + ar) * K + c8 * 4;

    const uint32_t s0 = sptr(sm);
    const uint32_t cpA = s0 + (ar * TSTR + c8 * 4) * 4;
    const uint32_t cpB = cpA + OP_SZ * 4;

    const int mloc = lane >> 3, rw = lane & 7;
    const uint32_t ard = s0 +
        ((wm + ((mloc & 1) << 3) + rw) * TSTR + ((mloc >> 1) << 2)) * 4;
    const uint32_t brd = s0 + OP_SZ * 4 +
        ((wn + ((lane >> 4) << 3) + rw) * TSTR + (((lane >> 3) & 1) << 2)) * 4;

    float acc[4][4][4];
#pragma unroll
    for (int mi = 0; mi < 4; mi++)
#pragma unroll
        for (int ni = 0; ni < 4; ni++)
#pragma unroll
            for (int t = 0; t < 4; t++) acc[mi][ni][t] = 0.f;

    const int nT = K >> 5;               // 32-K slabs
    auto issue = [&](int t) {
        const uint32_t off = (uint32_t)(t % 3) * STG_B;
        const int k0 = t << 5;
#pragma unroll
        for (int j = 0; j < 4; j++) {
            cpa16(cpA + off + j * (32 * TSTR * 4), Ap + (size_t)(32 * j) * K + k0);
            cpa16(cpB + off + j * (32 * TSTR * 4), Bp + (size_t)(32 * j) * K + k0);
        }
    };

    issue(0); cpa_commit();
    issue(1); cpa_commit();

    for (int t = 0; t < nT; t++) {
        asm volatile("cp.async.wait_group 1;");
        __syncthreads();

        const uint32_t off = (uint32_t)(t % 3) * STG_B;

        // ---- ks 0,1 ----
#pragma unroll
        for (int ks = 0; ks < 2; ks++) {
            unsigned af[4][4], bfr[8];
#pragma unroll
            for (int mi = 0; mi < 4; mi++)
                ldsm4(af[mi], ard + off + mi * (16 * TSTR * 4) + ks * 32);
            ldsm4(bfr,     brd + off + ks * 32);
            ldsm4(bfr + 4, brd + off + 16 * TSTR * 4 + ks * 32);
#pragma unroll
            for (int mi = 0; mi < 4; mi++)
#pragma unroll
                for (int ni = 0; ni < 4; ni++)
                    mma8b(acc[mi][ni], af[mi], bfr[2 * ni], bfr[2 * ni + 1]);
        }

        // ---- prefetch next-next slab; overlaps ks 2,3 math ----
        if (t + 2 < nT) issue(t + 2);
        cpa_commit();

        // ---- ks 2,3 ----
#pragma unroll
        for (int ks = 2; ks < 4; ks++) {
            unsigned af[4][4], bfr[8];
#pragma unroll
            for (int mi = 0; mi < 4; mi++)
                ldsm4(af[mi], ard + off + mi * (16 * TSTR * 4) + ks * 32);
            ldsm4(bfr,     brd + off + ks * 32);
            ldsm4(bfr + 4, brd + off + 16 * TSTR * 4 + ks * 32);
#pragma unroll
            for (int mi = 0; mi < 4; mi++)
#pragma unroll
                for (int ni = 0; ni < 4; ni++)
                    mma8b(acc[mi][ni], af[mi], bfr[2 * ni], bfr[2 * ni + 1]);
        }
    }

#pragma unroll
    for (int mi = 0; mi < 4; mi++) {
        int row = bm + wm + mi * 16 + g;
#pragma unroll
        for (int ni = 0; ni < 4; ni++) {
            int col = bn + wn + ni * 8 + 2 * c;
            float bv0 = bias ? bias[col] : 0.f;
            float bv1 = bias ? bias[col + 1] : 0.f;
            float* p0 = C + (size_t)row * N + col;
            float* p1 = C + (size_t)(row + 8) * N + col;
            p0[0] = acc[mi][ni][0] + bv0; p0[1] = acc[mi][ni][1] + bv1;
            p1[0] = acc[mi][ni][2] + bv0; p1[1] = acc[mi][ni][3] + bv1;
        }
    }
}

// fused q+kv projections: bx<8 -> q (N=1024), bx>=8 -> kv (N=2048)
__global__ __launch_bounds__(256) void gemm_qkv(
        const float* __restrict__ Ax, const float* __restrict__ Ac,
        const float* __restrict__ Bq, const float* __restrict__ Bkv,
        float* __restrict__ Cq, float* __restrict__ Ckv) {
    extern __shared__ float sm[];
    if (blockIdx.x < 8)
        gemm_core(Ax, Bq, nullptr, Cq, DIM, DIM, sm, blockIdx.x, blockIdx.y);
    else
        gemm_core(Ac, Bkv, nullptr, Ckv, 2 * DIM, DIM, sm,
                  blockIdx.x - 8, blockIdx.y);
}

__global__ __launch_bounds__(256) void gemm_tf32(
        const float* __restrict__ A, const float* __restrict__ Bt,
        const float* __restrict__ bias, float* __restrict__ C,
        int N, int K) {
    extern __shared__ float sm[];
    gemm_core(A, Bt, bias, C, N, K, sm, blockIdx.x, blockIdx.y);
}

// ---------------- fused LN: q-mode (LN+RoPE) and kv-mode (LN k + V^T) ------
__global__ __launch_bounds__(256) void ln_all_kernel(
        const float* __restrict__ Qbuf, const float* __restrict__ KVbuf,
        const float* __restrict__ qg, const float* __restrict__ qb,
        const float* __restrict__ kg, const float* __restrict__ kb_,
        float* __restrict__ Q, float* __restrict__ K, float* __restrict__ Vt) {
    const int h = blockIdx.y, rb = blockIdx.x * 64;
    const int tid = threadIdx.x, warp = tid >> 5, lane = tid & 31;

    if (blockIdx.z >= 4) {
        const int b = blockIdx.z - 4;
        const float ga0 = qg[lane], ga1 = qg[lane + 32];
        const float be0 = qb[lane], be1 = qb[lane + 32];
        const float invf = ex2(-(float)lane * (13.28771237954945f / 32.f));
#pragma unroll
        for (int j = 0; j < 8; j++) {
            const int s = rb + warp * 8 + j;
            const float* in = Qbuf + ((size_t)b * SEQ + s) * DIM + h * HD;
            float v0 = in[lane], v1 = in[lane + 32];
            float sum = v0 + v1;
#pragma unroll
            for (int o = 16; o; o >>= 1) sum += __shfl_xor_sync(0xffffffffu, sum, o);
            float mu = sum * (1.f / 64.f);
            float d0 = v0 - mu, d1 = v1 - mu;
            float vs = d0 * d0 + d1 * d1;
#pragma unroll
            for (int o = 16; o; o >>= 1) vs += __shfl_xor_sync(0xffffffffu, vs, o);
            float rstd = rsqrtf(vs * (1.f / 64.f) + 1e-5f);
            float y0 = d0 * rstd * ga0 + be0;
            float y1 = d1 * rstd * ga1 + be1;
            float sn, cs;
            sincosf((float)s * invf, &sn, &cs);
            float* outp = Q + ((size_t)(b * NHEAD + h) * SEQ + s) * HD;
            outp[lane]      = tf32f(y0 * cs - y1 * sn);
            outp[lane + 32] = tf32f(y0 * sn + y1 * cs);
        }
        return;
    }

    __shared__ float Vs[64 * 65];
    const int b = blockIdx.z;
    const float ga0 = kg[lane], ga1 = kg[lane + 32];
    const float be0 = kb_[lane], be1 = kb_[lane + 32];
#pragma unroll
    for (int j = 0; j < 8; j++) {
        const int kl  = warp * 8 + j;
        const int key = rb + kl;
        const float* kin = KVbuf + ((size_t)b * SEQ + key) * (2 * DIM) + h * HD;
        const float* vin = kin + DIM;
        float v0 = kin[lane], v1 = kin[lane + 32];
        float sum = v0 + v1;
#pragma unroll
        for (int o = 16; o; o >>= 1) sum += __shfl_xor_sync(0xffffffffu, sum, o);
        float mu = sum * (1.f / 64.f);
        float d0 = v0 - mu, d1 = v1 - mu;
        float vs = d0 * d0 + d1 * d1;
#pragma unroll
        for (int o = 16; o; o >>= 1) vs += __shfl_xor_sync(0xffffffffu, vs, o);
        float rstd = rsqrtf(vs * (1.f / 64.f) + 1e-5f);
        size_t ob = ((size_t)(b * NHEAD + h) * SEQ + key) * HD;
        K[ob + lane]      = tf32f(d0 * rstd * ga0 + be0);
        K[ob + lane + 32] = tf32f(d1 * rstd * ga1 + be1);
        Vs[lane * 65 + kl]        = tf32f(vin[lane]);
        Vs[(lane + 32) * 65 + kl] = tf32f(vin[lane + 32]);
    }
    __syncthreads();
    const int d = tid >> 2, c0 = (tid & 3) * 16;
    float* dst = Vt + ((size_t)((b * NHEAD + h) * HD + d)) * SEQ + rb + c0;
#pragma unroll
    for (int e = 0; e < 16; e += 4) {
        const float* s = &Vs[d * 65 + c0 + e];
        *(float4*)(dst + e) = make_float4(s[0], s[1], s[2], s[3]);
    }
}

// --------- flash attention: 128q x 64k, 4 warps x 32 rows (R12 form) -------
#define QIDX(r, col) ((r) * 64 + ((col) ^ (((r) & 7) << 2)))
#define VTIDX(d, key) ((d) * 64 + (((((key) >> 2) ^ ((d) & 7)) << 2) | ((key) & 3)))
#define FKV 8192
#define PWARP 2048
#define FLASH_SMEM ((2*FKV + 4*PWARP)*4)    // 98304 B

#define QSCALE (0.125f * 1.44269504088896340736f)

__global__ __launch_bounds__(128, 2) void flash_tf32(
        const float* __restrict__ Q, const float* __restrict__ K,
        const float* __restrict__ Vt, float* __restrict__ O) {
    extern __shared__ float stage[];

    const int qt = blockIdx.x, h = blockIdx.y, b = blockIdx.z;
    const int tid  = threadIdx.x;
    const int warp = tid >> 5, lane = tid & 31;
    const int g = lane >> 2, c = lane & 3;
    const int wm = warp * 32;

    const int mloc = lane >> 3, rw = lane & 7;
    uint32_t kb_base[4];
#pragma unroll
    for (int gi = 0; gi < 4; gi++) {
        int row = (gi * 2 + (mloc >> 1)) * 8 + rw;
        kb_base[gi] = (uint32_t)(row * 256) + ((((mloc & 1) << 4) ^ (rw << 4)));
    }
    const int Lr = lane & 15, h4 = lane >> 4, mmv = lane & 7;
    uint32_t vrow[4];
#pragma unroll
    for (int gi = 0; gi < 4; gi++) vrow[gi] = (uint32_t)((16 * gi + Lr) * 256);
    const uint32_t vlc = ((uint32_t)h4 << 4) ^ ((uint32_t)mmv << 4);
    float* Pw = stage + 2 * FKV + warp * PWARP;
    const uint32_t pwb = sptr(Pw);
    const uint32_t p_row = (uint32_t)((((lane >> 3) & 1) * 8 + rw) * 256);
    const uint32_t p_hi  = (uint32_t)((lane >> 4) << 4);
    const uint32_t p_rsw = (uint32_t)(rw << 4);

    const float* Qg  = Q  + ((size_t)(b * NHEAD + h) * SEQ + qt * 128) * HD;
    const float* Kg  = K  + (size_t)(b * NHEAD + h) * SEQ * HD;
    const float* Vtg = Vt + (size_t)(b * NHEAD + h) * HD * SEQ;

#pragma unroll
    for (int j = 0; j < 16; j++) {
        int i = tid + j * 128;
        int r = i >> 4, c4 = (i & 15) << 2;
        float* dst = (r < 64) ? &stage[QIDX(r, c4)] : &stage[4096 + QIDX(r - 64, c4)];
        cpa16(sptr(dst), Qg + (size_t)r * 64 + c4);
    }
    cpa_commit();
    asm volatile("cp.async.wait_group 0;");
    __syncthreads();

    unsigned qf[2][8][4];
#pragma unroll
    for (int mt = 0; mt < 2; mt++) {
        const int rbase = wm + mt * 16;
        const float* buf = (rbase < 64) ? stage : stage + 4096;
        const int rb = rbase & 63;
#pragma unroll
        for (int ks = 0; ks < 8; ks++) {
            int kk = ks * 8 + c;
            qf[mt][ks][0] = tf32(QSCALE * buf[QIDX(rb + g, kk)]);
            qf[mt][ks][1] = tf32(QSCALE * buf[QIDX(rb + 8 + g, kk)]);
            qf[mt][ks][2] = tf32(QSCALE * buf[QIDX(rb + g, kk + 4)]);
            qf[mt][ks][3] = tf32(QSCALE * buf[QIDX(rb + 8 + g, kk + 4)]);
        }
    }
    __syncthreads();

    auto issueKV = [&](int t) {
        float* Kb = stage + (t & 1) * FKV;
        float* Vb = Kb + 4096;
#pragma unroll
        for (int j = 0; j < 8; j++) {
            int i = tid + j * 128;
            int r = i >> 4, c4 = (i & 15) << 2;
            cpa16(sptr(&Kb[QIDX(r, c4)]), Kg + (size_t)(t * 64 + r) * 64 + c4);
            cpa16(sptr(&Vb[VTIDX(r, c4)]), Vtg + (size_t)r * SEQ + t * 64 + c4);
        }
    };

    issueKV(0); cpa_commit();
    issueKV(1); cpa_commit();

    float m_[2][2], l_[2][2], o[2][8][4];
#pragma unroll
    for (int mt = 0; mt < 2; mt++) {
        m_[mt][0] = -1e30f; m_[mt][1] = -1e30f;
        l_[mt][0] = 0.f;    l_[mt][1] = 0.f;
#pragma unroll
        for (int ni = 0; ni < 8; ni++)
#pragma unroll
            for (int t = 0; t < 4; t++) o[mt][ni][t] = 0.f;
    }

    const int nT = SEQ / 64;
    for (int kt = 0; kt < nT; kt++) {
        asm volatile("cp.async.wait_group 1;");
        __syncthreads();

        const uint32_t ksb = sptr(stage + (kt & 1) * FKV);
        const uint32_t vtb = ksb + 4096 * 4;

        float s[2][8][4];
#pragma unroll
        for (int mt = 0; mt < 2; mt++)
#pragma unroll
            for (int ni = 0; ni < 8; ni++)
#pragma unroll
                for (int t = 0; t < 4; t++) s[mt][ni][t] = 0.f;
#pragma unroll
        for (int ks = 0; ks < 8; ks++) {
            unsigned kbf[16];
#pragma unroll
            for (int gi = 0; gi < 4; gi++)
                ldsm4(&kbf[gi * 4], ksb + (kb_base[gi] ^ (uint32_t)(ks << 5)));
#pragma unroll
            for (int ni = 0; ni < 8; ni++) {
                mma8(s[0][ni], qf[0][ks], &kbf[ni * 2]);
                mma8(s[1][ni], qf[1][ks], &kbf[ni * 2]);
            }
        }

#pragma unroll
        for (int mt = 0; mt < 2; mt++) {
            float rm0 = -1e30f, rm1 = -1e30f;
#pragma unroll
            for (int ni = 0; ni < 8; ni++) {
                rm0 = fmaxf(rm0, fmaxf(s[mt][ni][0], s[mt][ni][1]));
                rm1 = fmaxf(rm1, fmaxf(s[mt][ni][2], s[mt][ni][3]));
            }
            rm0 = fmaxf(rm0, __shfl_xor_sync(0xffffffffu, rm0, 1));
            rm0 = fmaxf(rm0, __shfl_xor_sync(0xffffffffu, rm0, 2));
            rm1 = fmaxf(rm1, __shfl_xor_sync(0xffffffffu, rm1, 1));
            rm1 = fmaxf(rm1, __shfl_xor_sync(0xffffffffu, rm1, 2));
            float mn0 = fmaxf(m_[mt][0], rm0), mn1 = fmaxf(m_[mt][1], rm1);

            float ps0 = 0.f, ps1 = 0.f;
#pragma unroll
            for (int ni = 0; ni < 8; ni++) {
                s[mt][ni][0] = ex2(s[mt][ni][0] - mn0);
                s[mt][ni][1] = ex2(s[mt][ni][1] - mn0);
                s[mt][ni][2] = ex2(s[mt][ni][2] - mn1);
                s[mt][ni][3] = ex2(s[mt][ni][3] - mn1);
                ps0 += s[mt][ni][0] + s[mt][ni][1];
                ps1 += s[mt][ni][2] + s[mt][ni][3];
            }
            ps0 += __shfl_xor_sync(0xffffffffu, ps0, 1);
            ps0 += __shfl_xor_sync(0xffffffffu, ps0, 2);
            ps1 += __shfl_xor_sync(0xffffffffu, ps1, 1);
            ps1 += __shfl_xor_sync(0xffffffffu, ps1, 2);

            float al0 = ex2(m_[mt][0] - mn0), al1 = ex2(m_[mt][1] - mn1);
            m_[mt][0] = mn0; m_[mt][1] = mn1;
            l_[mt][0] = l_[mt][0] * al0 + ps0;
            l_[mt][1] = l_[mt][1] * al1 + ps1;
#pragma unroll
            for (int ni = 0; ni < 8; ni++) {
                o[mt][ni][0] *= al0; o[mt][ni][1] *= al0;
                o[mt][ni][2] *= al1; o[mt][ni][3] *= al1;
            }
        }

        {
            const int sw = g << 2;
#pragma unroll
            for (int mt = 0; mt < 2; mt++)
#pragma unroll
                for (int ni = 0; ni < 8; ni++) {
                    const int colb = ni * 8 + 2 * c;
                    *(float2*)&Pw[(mt * 16 + g) * 64 + (colb ^ sw)] =
                        make_float2(tf32f(s[mt][ni][0]), tf32f(s[mt][ni][1]));
                    *(float2*)&Pw[(mt * 16 + g + 8) * 64 + (colb ^ sw)] =
                        make_float2(tf32f(s[mt][ni][2]), tf32f(s[mt][ni][3]));
                }
        }
        __syncwarp();

#pragma unroll
        for (int ks = 0; ks < 8; ks++) {
            unsigned pa0[4], pa1[4];
            const uint32_t pofs = ((((uint32_t)ks << 5) | p_hi) ^ p_rsw);
            ldsm4(pa0, pwb + p_row + pofs);
            ldsm4(pa1, pwb + 4096 + p_row + pofs);
            const uint32_t xo = ((uint32_t)ks << 5) ^ vlc;
#pragma unroll
            for (int gi = 0; gi < 4; gi++) {
                unsigned vv[4];
                ldsm4(vv, vtb + vrow[gi] + xo);
                mma8b(o[0][2 * gi],     pa0, vv[0], vv[2]);
                mma8b(o[0][2 * gi + 1], pa0, vv[1], vv[3]);
                mma8b(o[1][2 * gi],     pa1, vv[0], vv[2]);
                mma8b(o[1][2 * gi + 1], pa1, vv[1], vv[3]);
            }
        }

        __syncthreads();
        if (kt + 2 < nT) issueKV(kt + 2);
        cpa_commit();
    }

#pragma unroll
    for (int mt = 0; mt < 2; mt++) {
        float inv0 = 1.f / l_[mt][0], inv1 = 1.f / l_[mt][1];
        int row0 = qt * 128 + wm + mt * 16 + g;
#pragma unroll
        for (int ni = 0; ni < 8; ni++) {
            int col = h * HD + ni * 8 + 2 * c;
            float* p0 = O + ((size_t)b * SEQ + row0) * DIM + col;
            float* p1 = O + ((size_t)b * SEQ + row0 + 8) * DIM + col;
            p0[0] = tf32f(o[mt][ni][0] * inv0);
            p0[1] = tf32f(o[mt][ni][1] * inv0);
            p1[0] = tf32f(o[mt][ni][2] * inv1);
            p1[1] = tf32f(o[mt][ni][3] * inv1);
        }
    }
}

// ---------------------------------------------------------------------------
extern "C" void kernel_launch(void* const* d_in, const int* in_sizes, int n_in,
                              void* d_out, int out_size) {
    const float* x        = (const float*)d_in[0];
    const float* context  = (const float*)d_in[1];
    const float* q_w      = (const float*)d_in[2];
    const float* kv_w     = (const float*)d_in[3];
    const float* qn_scale = (const float*)d_in[4];
    const float* qn_bias  = (const float*)d_in[5];
    const float* kn_scale = (const float*)d_in[6];
    const float* kn_bias  = (const float*)d_in[7];
    const float* proj_w   = (const float*)d_in[8];
    const float* proj_b   = (const float*)d_in[9];
    float* out = (float*)d_out;

    float *Qbuf, *KVbuf, *Q, *K, *V, *O, *xc, *cc, *qwt, *kvwt, *pwt;
    cudaGetSymbolAddress((void**)&Qbuf,  g_Qbuf);
    cudaGetSymbolAddress((void**)&KVbuf, g_KVbuf);
    cudaGetSymbolAddress((void**)&Q,     g_Q);
    cudaGetSymbolAddress((void**)&K,     g_K);
    cudaGetSymbolAddress((void**)&V,     g_V);
    cudaGetSymbolAddress((void**)&O,     g_O);
    cudaGetSymbolAddress((void**)&xc,    g_xc);
    cudaGetSymbolAddress((void**)&cc,    g_cc);
    cudaGetSymbolAddress((void**)&qwt,   g_qwt);
    cudaGetSymbolAddress((void**)&kvwt,  g_kvwt);
    cudaGetSymbolAddress((void**)&pwt,   g_pwt);

    cudaFuncSetAttribute(gemm_qkv,
        cudaFuncAttributeMaxDynamicSharedMemorySize, GEMM_SMEM);
    cudaFuncSetAttribute(gemm_tf32,
        cudaFuncAttributeMaxDynamicSharedMemorySize, GEMM_SMEM);
    cudaFuncSetAttribute(flash_tf32,
        cudaFuncAttributeMaxDynamicSharedMemorySize, FLASH_SMEM);

    // L1: weight transpose+round
    prep_w_kernel<<<dim3(2048, 1, 3), 256>>>(q_w, proj_w, kv_w, qwt, pwt, kvwt);
    // L2: round x; L3: round context
    round_kernel<<<2048, 256>>>((const float4*)x, (float4*)xc);
    round_kernel<<<2048, 256>>>((const float4*)context, (float4*)cc);
    // L4: fused q + kv projections (profiled slot)
    gemm_qkv<<<dim3(24, 64), 256, GEMM_SMEM>>>(xc, cc, qwt, kvwt, Qbuf, KVbuf);
    // L5: fused LN (q: LN+RoPE, kv: LN k + V^T)
    ln_all_kernel<<<dim3(32, 16, 8), 256>>>(
        Qbuf, KVbuf, qn_scale, qn_bias, kn_scale, kn_bias, Q, K, V);
    // L6: attention
    flash_tf32<<<dim3(SEQ / 128, NHEAD, BATCH), 128, FLASH_SMEM>>>(Q, K, V, O);
    // L7: out = O @ proj_w + proj_b
    gemm_tf32<<<dim3(8, 64), 256, GEMM_SMEM>>>(O, pwt, proj_b, out, DIM, DIM);
}

// round 17
// speedup vs baseline: 1.1427x; 1.0593x over previous
#include <cuda_runtime.h>
#include <math.h>
#include <stdint.h>

#define BATCH 4
#define SEQ   2048
#define DIM   1024
#define NHEAD 16
#define HD    64
#define ROWS  (BATCH*SEQ)   // 8192

// ---------------- scratch (device globals; no allocation allowed) ----------
__device__ float g_Q[(size_t)ROWS * DIM];           // [B,H,S,Hd] tf32
__device__ float g_K[(size_t)ROWS * DIM];           // [B,H,Sc,Hd] tf32
__device__ float g_V[(size_t)ROWS * DIM];           // [B,H,Hd,Sc] transposed tf32
__device__ float g_O[(size_t)ROWS * DIM];           // [B,S,H*Hd] tf32
__device__ float g_xc[(size_t)ROWS * DIM];          // tf32 x
__device__ float g_cc[(size_t)ROWS * DIM];          // tf32 context
__device__ float g_qwt[(size_t)DIM * DIM];          // q_w^T   [N][K] tf32
__device__ float g_kvwt[(size_t)2 * DIM * DIM];     // kv_w^T  [2N][K] tf32
__device__ float g_pwt[(size_t)DIM * DIM];          // proj_w^T tf32

// ---------------- helpers ---------------------------------------------------
__device__ __forceinline__ unsigned tf32(float x) {
    unsigned u;
    asm("cvt.rna.tf32.f32 %0, %1;" : "=r"(u) : "f"(x));
    return u;
}
__device__ __forceinline__ float tf32f(float x) { return __uint_as_float(tf32(x)); }
__device__ __forceinline__ float ex2(float x) {
    float y;
    asm("ex2.approx.f32 %0, %1;" : "=f"(y) : "f"(x));
    return y;
}

__device__ __forceinline__ void mma8(float* d, const unsigned* a, const unsigned* b) {
    asm volatile(
        "mma.sync.aligned.m16n8k8.row.col.f32.tf32.tf32.f32 "
        "{%0,%1,%2,%3}, {%4,%5,%6,%7}, {%8,%9}, {%0,%1,%2,%3};"
        : "+f"(d[0]), "+f"(d[1]), "+f"(d[2]), "+f"(d[3])
        : "r"(a[0]), "r"(a[1]), "r"(a[2]), "r"(a[3]), "r"(b[0]), "r"(b[1]));
}
__device__ __forceinline__ void mma8b(float* d, const unsigned* a,
                                      unsigned b0, unsigned b1) {
    asm volatile(
        "mma.sync.aligned.m16n8k8.row.col.f32.tf32.tf32.f32 "
        "{%0,%1,%2,%3}, {%4,%5,%6,%7}, {%8,%9}, {%0,%1,%2,%3};"
        : "+f"(d[0]), "+f"(d[1]), "+f"(d[2]), "+f"(d[3])
        : "r"(a[0]), "r"(a[1]), "r"(a[2]), "r"(a[3]), "r"(b0), "r"(b1));
}
__device__ __forceinline__ void ldsm4(unsigned* r, uint32_t addr) {
    asm volatile("ldmatrix.sync.aligned.m8n8.x4.shared.b16 {%0,%1,%2,%3}, [%4];"
        : "=r"(r[0]), "=r"(r[1]), "=r"(r[2]), "=r"(r[3]) : "r"(addr));
}
__device__ __forceinline__ void cpa16(uint32_t s, const void* g) {
    asm volatile("cp.async.cg.shared.global [%0], [%1], 16;" :: "r"(s), "l"(g));
}
__device__ __forceinline__ void cpa_commit() {
    asm volatile("cp.async.commit_group;");
}
__device__ __forceinline__ uint32_t sptr(const void* p) {
    return (uint32_t)__cvta_generic_to_shared(p);
}

// ---------------- prep kernels ----------------------------------------------
__global__ void prep_w_kernel(
        const float* __restrict__ qw,  const float* __restrict__ pw,
        const float* __restrict__ kvw,
        float* __restrict__ qwt, float* __restrict__ pwt,
        float* __restrict__ kvwt) {
    const int z = blockIdx.z;
    const float* W; float* Wt; int N;
    if (z == 0)      { W = qw;  Wt = qwt;  N = DIM; }
    else if (z == 1) { W = pw;  Wt = pwt;  N = DIM; }
    else             { W = kvw; Wt = kvwt; N = 2 * DIM; }
    const int ntx = N / 32;
    const int tile = blockIdx.x;
    if (tile >= (DIM / 32) * ntx) return;
    const int kx = (tile / ntx) * 32, ny = (tile % ntx) * 32;
    __shared__ float t[32][33];
    const int tx = threadIdx.x & 31, ty = threadIdx.x >> 5;
#pragma unroll
    for (int j = 0; j < 32; j += 8)
        t[ty + j][tx] = tf32f(W[(size_t)(kx + ty + j) * N + ny + tx]);
    __syncthreads();
#pragma unroll
    for (int j = 0; j < 32; j += 8)
        Wt[(size_t)(ny + ty + j) * DIM + kx + tx] = t[tx][ty + j];
}

__global__ void round_kernel(const float4* __restrict__ in,
                             float4* __restrict__ out) {
    const int n4 = ROWS * DIM / 4;
    for (int i = blockIdx.x * blockDim.x + threadIdx.x; i < n4;
         i += gridDim.x * blockDim.x) {
        float4 v = in[i];
        v.x = tf32f(v.x); v.y = tf32f(v.y);
        v.z = tf32f(v.z); v.w = tf32f(v.w);
        out[i] = v;
    }
}

// ---------------- TF32 GEMM mainloop config (K-tile 32, 3-stage) -----------
#define TSTR 36
#define OP_SZ (128*TSTR)
#define STG_B (2*OP_SZ*4)              // 36864 B per stage
#define GEMM_SMEM (3*STG_B)            // 110592 B
#define EPAD 132

// mainloop macro-free shared implementation (acc left in registers)
#define GEMM_MAINLOOP(Aptr, Bptr)                                              \
    const int ar = tid >> 3;                                                   \
    const int c8 = tid & 7;                                                    \
    const float* Ap = (Aptr) + (size_t)(bm + ar) * DIM + c8 * 4;               \
    const float* Bp = (Bptr) + (size_t)(bn + ar) * DIM + c8 * 4;               \
    const uint32_t s0a = sptr(sm);                                             \
    const uint32_t cpA = s0a + (ar * TSTR + c8 * 4) * 4;                       \
    const uint32_t cpB = cpA + OP_SZ * 4;                                      \
    const int mloc = lane >> 3, rw = lane & 7;                                 \
    const uint32_t ard = s0a +                                                 \
        ((wm + ((mloc & 1) << 3) + rw) * TSTR + ((mloc >> 1) << 2)) * 4;       \
    const uint32_t brd = s0a + OP_SZ * 4 +                                     \
        ((wn + ((lane >> 4) << 3) + rw) * TSTR + (((lane >> 3) & 1) << 2)) * 4;\
    float acc[4][4][4];                                                        \
    _Pragma("unroll")                                                          \
    for (int mi = 0; mi < 4; mi++)                                             \
        _Pragma("unroll")                                                      \
        for (int ni = 0; ni < 4; ni++)                                         \
            _Pragma("unroll")                                                  \
            for (int t = 0; t < 4; t++) acc[mi][ni][t] = 0.f;                  \
    const int nT = DIM >> 5;                                                   \
    auto issue = [&](int t) {                                                  \
        const uint32_t off = (uint32_t)(t % 3) * STG_B;                        \
        const int k0 = t << 5;                                                 \
        _Pragma("unroll")                                                      \
        for (int j = 0; j < 4; j++) {                                          \
            cpa16(cpA + off + j * (32 * TSTR * 4),                             \
                  Ap + (size_t)(32 * j) * DIM + k0);                           \
            cpa16(cpB + off + j * (32 * TSTR * 4),                             \
                  Bp + (size_t)(32 * j) * DIM + k0);                           \
        }                                                                      \
    };                                                                         \
    issue(0); cpa_commit();                                                    \
    issue(1); cpa_commit();                                                    \
    for (int t = 0; t < nT; t++) {                                             \
        asm volatile("cp.async.wait_group 1;");                                \
        __syncthreads();                                                       \
        const uint32_t off = (uint32_t)(t % 3) * STG_B;                        \
        _Pragma("unroll")                                                      \
        for (int ks = 0; ks < 2; ks++) {                                       \
            unsigned af[4][4], bfr[8];                                         \
            _Pragma("unroll")                                                  \
            for (int mi = 0; mi < 4; mi++)                                     \
                ldsm4(af[mi], ard + off + mi * (16 * TSTR * 4) + ks * 32);     \
            ldsm4(bfr,     brd + off + ks * 32);                               \
            ldsm4(bfr + 4, brd + off + 16 * TSTR * 4 + ks * 32);               \
            _Pragma("unroll")                                                  \
            for (int mi = 0; mi < 4; mi++)                                     \
                _Pragma("unroll")                                              \
                for (int ni = 0; ni < 4; ni++)                                 \
                    mma8b(acc[mi][ni], af[mi], bfr[2 * ni], bfr[2 * ni + 1]);  \
        }                                                                      \
        if (t + 2 < nT) issue(t + 2);                                          \
        cpa_commit();                                                          \
        _Pragma("unroll")                                                      \
        for (int ks = 2; ks < 4; ks++) {                                       \
            unsigned af[4][4], bfr[8];                                         \
            _Pragma("unroll")                                                  \
            for (int mi = 0; mi < 4; mi++)                                     \
                ldsm4(af[mi], ard + off + mi * (16 * TSTR * 4) + ks * 32);     \
            ldsm4(bfr,     brd + off + ks * 32);                               \
            ldsm4(bfr + 4, brd + off + 16 * TSTR * 4 + ks * 32);               \
            _Pragma("unroll")                                                  \
            for (int mi = 0; mi < 4; mi++)                                     \
                _Pragma("unroll")                                              \
                for (int ni = 0; ni < 4; ni++)                                 \
                    mma8b(acc[mi][ni], af[mi], bfr[2 * ni], bfr[2 * ni + 1]);  \
        }                                                                      \
    }

// ---- qkv GEMM with fused LN/RoPE/V-transpose epilogue ---------------------
__global__ __launch_bounds__(256, 2) void gemm_qkv_fused(
        const float* __restrict__ Ax, const float* __restrict__ Ac,
        const float* __restrict__ Bq, const float* __restrict__ Bkv,
        const float* __restrict__ qg, const float* __restrict__ qb,
        const float* __restrict__ kg, const float* __restrict__ kb,
        float* __restrict__ Qo, float* __restrict__ Ko, float* __restrict__ Vto) {
    extern __shared__ float sm[];
    const int bx = blockIdx.x, by = blockIdx.y;
    const int tid  = threadIdx.x;
    const int warp = tid >> 5, lane = tid & 31;
    const int g = lane >> 2, c = lane & 3;
    const int wm = (warp >> 2) * 64, wn = (warp & 3) * 32;
    const int bm = by * 128;
    const int bn = (bx < 8 ? bx : bx - 8) * 128;

    const float* A  = (bx < 8) ? Ax : Ac;
    const float* Bt = (bx < 8) ? Bq : Bkv;

    GEMM_MAINLOOP(A, Bt)

    // ---- stage acc to smem (128 x 132) ----
    __syncthreads();
#pragma unroll
    for (int mi = 0; mi < 4; mi++) {
        int r0 = wm + mi * 16 + g;
#pragma unroll
        for (int ni = 0; ni < 4; ni++) {
            int col = wn + ni * 8 + 2 * c;
            *(float2*)&sm[r0 * EPAD + col] =
                make_float2(acc[mi][ni][0], acc[mi][ni][1]);
            *(float2*)&sm[(r0 + 8) * EPAD + col] =
                make_float2(acc[mi][ni][2], acc[mi][ni][3]);
        }
    }
    __syncthreads();

    const int b = by >> 4, s0 = (by & 15) << 7;

    if (bx < 16) {
        // ---- LN path: q (bx<8, +RoPE) or k (8<=bx<16) ----
        const bool isq = (bx < 8);
        const int h0 = (isq ? bx : bx - 8) * 2;
        const float* gmv = isq ? qg : kg;
        const float* btv = isq ? qb : kb;
        const float ga0 = gmv[lane], ga1 = gmv[lane + 32];
        const float be0 = btv[lane], be1 = btv[lane + 32];
        const float invf = ex2(-(float)lane * (13.28771237954945f / 32.f));
        float* dstbase = isq ? Qo : Ko;

        for (int it = 0; it < 32; it++) {
            const int rh = warp * 32 + it;
            const int r = rh >> 1, hh = rh & 1;
            float v0 = sm[r * EPAD + hh * 64 + lane];
            float v1 = sm[r * EPAD + hh * 64 + lane + 32];
            float sum = v0 + v1;
#pragma unroll
            for (int o = 16; o; o >>= 1) sum += __shfl_xor_sync(0xffffffffu, sum, o);
            float mu = sum * (1.f / 64.f);
            float d0 = v0 - mu, d1 = v1 - mu;
            float vs = d0 * d0 + d1 * d1;
#pragma unroll
            for (int o = 16; o; o >>= 1) vs += __shfl_xor_sync(0xffffffffu, vs, o);
            float rstd = rsqrtf(vs * (1.f / 64.f) + 1e-5f);
            float y0 = d0 * rstd * ga0 + be0;
            float y1 = d1 * rstd * ga1 + be1;
            float* outp = dstbase +
                ((size_t)(b * NHEAD + h0 + hh) * SEQ + s0 + r) * HD;
            if (isq) {
                float sn, cs;
                sincosf((float)(s0 + r) * invf, &sn, &cs);
                outp[lane]      = tf32f(y0 * cs - y1 * sn);
                outp[lane + 32] = tf32f(y0 * sn + y1 * cs);
            } else {
                outp[lane]      = tf32f(y0);
                outp[lane + 32] = tf32f(y1);
            }
        }
    } else {
        // ---- V path: tf32-round + transposed write to Vt[b,h,d,key] ----
        const int h0 = (bx - 16) * 2;
        const int d = tid >> 2, c0 = (tid & 3) * 32;
#pragma unroll
        for (int hh = 0; hh < 2; hh++) {
            float* dst = Vto +
                ((size_t)((b * NHEAD + h0 + hh) * HD + d)) * SEQ + s0 + c0;
            const float* src = sm + hh * 64 + d;
#pragma unroll
            for (int e = 0; e < 32; e += 4) {
                *(float4*)(dst + e) = make_float4(
                    tf32f(src[(c0 + e)     * EPAD]),
                    tf32f(src[(c0 + e + 1) * EPAD]),
                    tf32f(src[(c0 + e + 2) * EPAD]),
                    tf32f(src[(c0 + e + 3) * EPAD]));
            }
        }
    }
}

// ---- plain GEMM (proj): standard epilogue ---------------------------------
__global__ __launch_bounds__(256, 2) void gemm_tf32(
        const float* __restrict__ A, const float* __restrict__ Bt,
        const float* __restrict__ bias, float* __restrict__ C, int N) {
    extern __shared__ float sm[];
    const int bx = blockIdx.x, by = blockIdx.y;
    const int tid  = threadIdx.x;
    const int warp = tid >> 5, lane = tid & 31;
    const int g = lane >> 2, c = lane & 3;
    const int wm = (warp >> 2) * 64, wn = (warp & 3) * 32;
    const int bm = by * 128, bn = bx * 128;

    GEMM_MAINLOOP(A, Bt)

#pragma unroll
    for (int mi = 0; mi < 4; mi++) {
        int row = bm + wm + mi * 16 + g;
#pragma unroll
        for (int ni = 0; ni < 4; ni++) {
            int col = bn + wn + ni * 8 + 2 * c;
            float bv0 = bias ? bias[col] : 0.f;
            float bv1 = bias ? bias[col + 1] : 0.f;
            float* p0 = C + (size_t)row * N + col;
            float* p1 = C + (size_t)(row + 8) * N + col;
            p0[0] = acc[mi][ni][0] + bv0; p0[1] = acc[mi][ni][1] + bv1;
            p1[0] = acc[mi][ni][2] + bv0; p1[1] = acc[mi][ni][3] + bv1;
        }
    }
}

// --------- flash attention: 128q x 64k, 4 warps x 32 rows (R12 form) -------
#define QIDX(r, col) ((r) * 64 + ((col) ^ (((r) & 7) << 2)))
#define VTIDX(d, key) ((d) * 64 + (((((key) >> 2) ^ ((d) & 7)) << 2) | ((key) & 3)))
#define FKV 8192
#define PWARP 2048
#define FLASH_SMEM ((2*FKV + 4*PWARP)*4)    // 98304 B

#define QSCALE (0.125f * 1.44269504088896340736f)

__global__ __launch_bounds__(128, 2) void flash_tf32(
        const float* __restrict__ Q, const float* __restrict__ K,
        const float* __restrict__ Vt, float* __restrict__ O) {
    extern __shared__ float stage[];

    const int qt = blockIdx.x, h = blockIdx.y, b = blockIdx.z;
    const int tid  = threadIdx.x;
    const int warp = tid >> 5, lane = tid & 31;
    const int g = lane >> 2, c = lane & 3;
    const int wm = warp * 32;

    const int mloc = lane >> 3, rw = lane & 7;
    uint32_t kb_base[4];
#pragma unroll
    for (int gi = 0; gi < 4; gi++) {
        int row = (gi * 2 + (mloc >> 1)) * 8 + rw;
        kb_base[gi] = (uint32_t)(row * 256) + ((((mloc & 1) << 4) ^ (rw << 4)));
    }
    const int Lr = lane & 15, h4 = lane >> 4, mmv = lane & 7;
    uint32_t vrow[4];
#pragma unroll
    for (int gi = 0; gi < 4; gi++) vrow[gi] = (uint32_t)((16 * gi + Lr) * 256);
    const uint32_t vlc = ((uint32_t)h4 << 4) ^ ((uint32_t)mmv << 4);
    float* Pw = stage + 2 * FKV + warp * PWARP;
    const uint32_t pwb = sptr(Pw);
    const uint32_t p_row = (uint32_t)((((lane >> 3) & 1) * 8 + rw) * 256);
    const uint32_t p_hi  = (uint32_t)((lane >> 4) << 4);
    const uint32_t p_rsw = (uint32_t)(rw << 4);

    const float* Qg  = Q  + ((size_t)(b * NHEAD + h) * SEQ + qt * 128) * HD;
    const float* Kg  = K  + (size_t)(b * NHEAD + h) * SEQ * HD;
    const float* Vtg = Vt + (size_t)(b * NHEAD + h) * HD * SEQ;

#pragma unroll
    for (int j = 0; j < 16; j++) {
        int i = tid + j * 128;
        int r = i >> 4, c4 = (i & 15) << 2;
        float* dst = (r < 64) ? &stage[QIDX(r, c4)] : &stage[4096 + QIDX(r - 64, c4)];
        cpa16(sptr(dst), Qg + (size_t)r * 64 + c4);
    }
    cpa_commit();
    asm volatile("cp.async.wait_group 0;");
    __syncthreads();

    unsigned qf[2][8][4];
#pragma unroll
    for (int mt = 0; mt < 2; mt++) {
        const int rbase = wm + mt * 16;
        const float* buf = (rbase < 64) ? stage : stage + 4096;
        const int rb = rbase & 63;
#pragma unroll
        for (int ks = 0; ks < 8; ks++) {
            int kk = ks * 8 + c;
            qf[mt][ks][0] = tf32(QSCALE * buf[QIDX(rb + g, kk)]);
            qf[mt][ks][1] = tf32(QSCALE * buf[QIDX(rb + 8 + g, kk)]);
            qf[mt][ks][2] = tf32(QSCALE * buf[QIDX(rb + g, kk + 4)]);
            qf[mt][ks][3] = tf32(QSCALE * buf[QIDX(rb + 8 + g, kk + 4)]);
        }
    }
    __syncthreads();

    auto issueKV = [&](int t) {
        float* Kb = stage + (t & 1) * FKV;
        float* Vb = Kb + 4096;
#pragma unroll
        for (int j = 0; j < 8; j++) {
            int i = tid + j * 128;
            int r = i >> 4, c4 = (i & 15) << 2;
            cpa16(sptr(&Kb[QIDX(r, c4)]), Kg + (size_t)(t * 64 + r) * 64 + c4);
            cpa16(sptr(&Vb[VTIDX(r, c4)]), Vtg + (size_t)r * SEQ + t * 64 + c4);
        }
    };

    issueKV(0); cpa_commit();
    issueKV(1); cpa_commit();

    float m_[2][2], l_[2][2], o[2][8][4];
#pragma unroll
    for (int mt = 0; mt < 2; mt++) {
        m_[mt][0] = -1e30f; m_[mt][1] = -1e30f;
        l_[mt][0] = 0.f;    l_[mt][1] = 0.f;
#pragma unroll
        for (int ni = 0; ni < 8; ni++)
#pragma unroll
            for (int t = 0; t < 4; t++) o[mt][ni][t] = 0.f;
    }

    const int nT = SEQ / 64;
    for (int kt = 0; kt < nT; kt++) {
        asm volatile("cp.async.wait_group 1;");
        __syncthreads();

        const uint32_t ksb = sptr(stage + (kt & 1) * FKV);
        const uint32_t vtb = ksb + 4096 * 4;

        float s[2][8][4];
#pragma unroll
        for (int mt = 0; mt < 2; mt++)
#pragma unroll
            for (int ni = 0; ni < 8; ni++)
#pragma unroll
                for (int t = 0; t < 4; t++) s[mt][ni][t] = 0.f;
#pragma unroll
        for (int ks = 0; ks < 8; ks++) {
            unsigned kbf[16];
#pragma unroll
            for (int gi = 0; gi < 4; gi++)
                ldsm4(&kbf[gi * 4], ksb + (kb_base[gi] ^ (uint32_t)(ks << 5)));
#pragma unroll
            for (int ni = 0; ni < 8; ni++) {
                mma8(s[0][ni], qf[0][ks], &kbf[ni * 2]);
                mma8(s[1][ni], qf[1][ks], &kbf[ni * 2]);
            }
        }

#pragma unroll
        for (int mt = 0; mt < 2; mt++) {
            float rm0 = -1e30f, rm1 = -1e30f;
#pragma unroll
            for (int ni = 0; ni < 8; ni++) {
                rm0 = fmaxf(rm0, fmaxf(s[mt][ni][0], s[mt][ni][1]));
                rm1 = fmaxf(rm1, fmaxf(s[mt][ni][2], s[mt][ni][3]));
            }
            rm0 = fmaxf(rm0, __shfl_xor_sync(0xffffffffu, rm0, 1));
            rm0 = fmaxf(rm0, __shfl_xor_sync(0xffffffffu, rm0, 2));
            rm1 = fmaxf(rm1, __shfl_xor_sync(0xffffffffu, rm1, 1));
            rm1 = fmaxf(rm1, __shfl_xor_sync(0xffffffffu, rm1, 2));
            float mn0 = fmaxf(m_[mt][0], rm0), mn1 = fmaxf(m_[mt][1], rm1);

            float ps0 = 0.f, ps1 = 0.f;
#pragma unroll
            for (int ni = 0; ni < 8; ni++) {
                s[mt][ni][0] = ex2(s[mt][ni][0] - mn0);
                s[mt][ni][1] = ex2(s[mt][ni][1] - mn0);
                s[mt][ni][2] = ex2(s[mt][ni][2] - mn1);
                s[mt][ni][3] = ex2(s[mt][ni][3] - mn1);
                ps0 += s[mt][ni][0] + s[mt][ni][1];
                ps1 += s[mt][ni][2] + s[mt][ni][3];
            }
            ps0 += __shfl_xor_sync(0xffffffffu, ps0, 1);
            ps0 += __shfl_xor_sync(0xffffffffu, ps0, 2);
            ps1 += __shfl_xor_sync(0xffffffffu, ps1, 1);
            ps1 += __shfl_xor_sync(0xffffffffu, ps1, 2);

            float al0 = ex2(m_[mt][0] - mn0), al1 = ex2(m_[mt][1] - mn1);
            m_[mt][0] = mn0; m_[mt][1] = mn1;
            l_[mt][0] = l_[mt][0] * al0 + ps0;
            l_[mt][1] = l_[mt][1] * al1 + ps1;
#pragma unroll
            for (int ni = 0; ni < 8; ni++) {
                o[mt][ni][0] *= al0; o[mt][ni][1] *= al0;
                o[mt][ni][2] *= al1; o[mt][ni][3] *= al1;
            }
        }

        {
            const int sw = g << 2;
#pragma unroll
            for (int mt = 0; mt < 2; mt++)
#pragma unroll
                for (int ni = 0; ni < 8; ni++) {
                    const int colb = ni * 8 + 2 * c;
                    *(float2*)&Pw[(mt * 16 + g) * 64 + (colb ^ sw)] =
                        make_float2(tf32f(s[mt][ni][0]), tf32f(s[mt][ni][1]));
                    *(float2*)&Pw[(mt * 16 + g + 8) * 64 + (colb ^ sw)] =
                        make_float2(tf32f(s[mt][ni][2]), tf32f(s[mt][ni][3]));
                }
        }
        __syncwarp();

#pragma unroll
        for (int ks = 0; ks < 8; ks++) {
            unsigned pa0[4], pa1[4];
            const uint32_t pofs = ((((uint32_t)ks << 5) | p_hi) ^ p_rsw);
            ldsm4(pa0, pwb + p_row + pofs);
            ldsm4(pa1, pwb + 4096 + p_row + pofs);
            const uint32_t xo = ((uint32_t)ks << 5) ^ vlc;
#pragma unroll
            for (int gi = 0; gi < 4; gi++) {
                unsigned vv[4];
                ldsm4(vv, vtb + vrow[gi] + xo);
                mma8b(o[0][2 * gi],     pa0, vv[0], vv[2]);
                mma8b(o[0][2 * gi + 1], pa0, vv[1], vv[3]);
                mma8b(o[1][2 * gi],     pa1, vv[0], vv[2]);
                mma8b(o[1][2 * gi + 1], pa1, vv[1], vv[3]);
            }
        }

        __syncthreads();
        if (kt + 2 < nT) issueKV(kt + 2);
        cpa_commit();
    }

#pragma unroll
    for (int mt = 0; mt < 2; mt++) {
        float inv0 = 1.f / l_[mt][0], inv1 = 1.f / l_[mt][1];
        int row0 = qt * 128 + wm + mt * 16 + g;
#pragma unroll
        for (int ni = 0; ni < 8; ni++) {
            int col = h * HD + ni * 8 + 2 * c;
            float* p0 = O + ((size_t)b * SEQ + row0) * DIM + col;
            float* p1 = O + ((size_t)b * SEQ + row0 + 8) * DIM + col;
            p0[0] = tf32f(o[mt][ni][0] * inv0);
            p0[1] = tf32f(o[mt][ni][1] * inv0);
            p1[0] = tf32f(o[mt][ni][2] * inv1);
            p1[1] = tf32f(o[mt][ni][3] * inv1);
        }
    }
}

// ---------------------------------------------------------------------------
extern "C" void kernel_launch(void* const* d_in, const int* in_sizes, int n_in,
                              void* d_out, int out_size) {
    const float* x        = (const float*)d_in[0];
    const float* context  = (const float*)d_in[1];
    const float* q_w      = (const float*)d_in[2];
    const float* kv_w     = (const float*)d_in[3];
    const float* qn_scale = (const float*)d_in[4];
    const float* qn_bias  = (const float*)d_in[5];
    const float* kn_scale = (const float*)d_in[6];
    const float* kn_bias  = (const float*)d_in[7];
    const float* proj_w   = (const float*)d_in[8];
    const float* proj_b   = (const float*)d_in[9];
    float* out = (float*)d_out;

    float *Q, *K, *V, *O, *xc, *cc, *qwt, *kvwt, *pwt;
    cudaGetSymbolAddress((void**)&Q,    g_Q);
    cudaGetSymbolAddress((void**)&K,    g_K);
    cudaGetSymbolAddress((void**)&V,    g_V);
    cudaGetSymbolAddress((void**)&O,    g_O);
    cudaGetSymbolAddress((void**)&xc,   g_xc);
    cudaGetSymbolAddress((void**)&cc,   g_cc);
    cudaGetSymbolAddress((void**)&qwt,  g_qwt);
    cudaGetSymbolAddress((void**)&kvwt, g_kvwt);
    cudaGetSymbolAddress((void**)&pwt,  g_pwt);

    cudaFuncSetAttribute(gemm_qkv_fused,
        cudaFuncAttributeMaxDynamicSharedMemorySize, GEMM_SMEM);
    cudaFuncSetAttribute(gemm_tf32,
        cudaFuncAttributeMaxDynamicSharedMemorySize, GEMM_SMEM);
    cudaFuncSetAttribute(flash_tf32,
        cudaFuncAttributeMaxDynamicSharedMemorySize, FLASH_SMEM);

    // L1: weight transpose+round
    prep_w_kernel<<<dim3(2048, 1, 3), 256>>>(q_w, proj_w, kv_w, qwt, pwt, kvwt);
    // L2/L3: round x, context
    round_kernel<<<2048, 256>>>((const float4*)x, (float4*)xc);
    round_kernel<<<2048, 256>>>((const float4*)context, (float4*)cc);
    // L4: fused q + kv projections + LN/RoPE/V^T (profiled slot)
    gemm_qkv_fused<<<dim3(24, 64), 256, GEMM_SMEM>>>(
        xc, cc, qwt, kvwt, qn_scale, qn_bias, kn_scale, kn_bias, Q, K, V);
    // L5: attention
    flash_tf32<<<dim3(SEQ / 128, NHEAD, BATCH), 128, FLASH_SMEM>>>(Q, K, V, O);
    // L6: out = O @ proj_w + proj_b
    gemm_tf32<<<dim3(8, 64), 256, GEMM_SMEM>>>(O, pwt, proj_b, out, DIM);
}